// round 2
// baseline (speedup 1.0000x reference)
#include <cuda_runtime.h>
#include <math.h>

// Linear_bin: binarized 5-layer MLP, B=32768, 64->2048->1024->512->64->1.
// Hidden activations are exactly {0,1} bits; weights are sign() = {-1,0,+1}.
// L1: fp32 FMA GEMM (prefetched) -> bitpack.  L2-L4: exact bitwise popcount GEMMs
// with double-buffered weight loads and 2 output columns per thread.
// L5 + sigmoid fused into the L4 kernel.

#define BATCH 32768
#define EPSBN 1e-5f

// ---------------- scratch (static device globals; no allocation) ----------------
__device__ __align__(16) float    d_s1k[64 * 2048];   // sign(w1), layout [(k>>2)*2048+j]*4+(k&3)
__device__ __align__(16) unsigned d_p2v[64 * 1024];   // w2>0 masks, [(w>>2)*1024+j]*4+(w&3)
__device__ __align__(16) unsigned d_z2 [64 * 1024];   // w2==0 masks, [w*1024+j]
__device__ int d_zf2[1024];
__device__ __align__(16) unsigned d_p3v[32 * 512];
__device__ __align__(16) unsigned d_z3 [32 * 512];
__device__ int d_zf3[512];
__device__ unsigned d_p4[64 * 16];
__device__ unsigned d_n4[64 * 16];
__device__ __align__(16) unsigned d_h1[BATCH * 64];   // layer-1 output bits
__device__ __align__(16) unsigned d_h2[BATCH * 32];
__device__ __align__(16) unsigned d_h3[BATCH * 16];

// ---------------- weight preprocessing (re-run every launch; deterministic) -----
__global__ void pack_s1(const float* __restrict__ w1) {
    int idx = blockIdx.x * 256 + threadIdx.x;          // 131072 threads
    int j = idx & 2047, k = idx >> 11;
    float v = w1[j * 64 + k];
    float s = (v > 0.f) ? 1.f : ((v < 0.f) ? -1.f : 0.f);
    d_s1k[((k >> 2) * 2048 + j) * 4 + (k & 3)] = s;
}

__global__ void pack_w(const float* __restrict__ w2, const float* __restrict__ w3,
                       const float* __restrict__ w4) {
    int idx = blockIdx.x * 256 + threadIdx.x;          // 82944 threads exactly
    if (idx < 65536) {                                 // layer 2: 1024 x 64 words
        int j = idx >> 6, w = idx & 63;
        unsigned p = 0, z = 0;
        #pragma unroll
        for (int i = 0; i < 32; i++) {
            float v = w2[j * 2048 + w * 32 + i];
            if (v > 0.f) p |= (1u << i);
            if (v == 0.f) z |= (1u << i);
        }
        d_p2v[((w >> 2) * 1024 + j) * 4 + (w & 3)] = p;
        d_z2[w * 1024 + j] = z;
    } else if (idx < 81920) {                          // layer 3: 512 x 32 words
        int t = idx - 65536; int j = t >> 5, w = t & 31;
        unsigned p = 0, z = 0;
        #pragma unroll
        for (int i = 0; i < 32; i++) {
            float v = w3[j * 1024 + w * 32 + i];
            if (v > 0.f) p |= (1u << i);
            if (v == 0.f) z |= (1u << i);
        }
        d_p3v[((w >> 2) * 512 + j) * 4 + (w & 3)] = p;
        d_z3[w * 512 + j] = z;
    } else {                                           // layer 4: 64 x 16 words
        int t = idx - 81920; int j = t >> 4, w = t & 15;
        unsigned p = 0, n = 0;
        #pragma unroll
        for (int i = 0; i < 32; i++) {
            float v = w4[j * 512 + w * 32 + i];
            if (v > 0.f) p |= (1u << i);
            if (v < 0.f) n |= (1u << i);
        }
        d_p4[j * 16 + w] = p;
        d_n4[j * 16 + w] = n;
    }
}

__global__ void zflags_kernel() {
    int idx = blockIdx.x * 256 + threadIdx.x;          // 1536 threads
    if (idx < 1024) {
        unsigned o = 0;
        for (int k = 0; k < 64; k++) o |= d_z2[k * 1024 + idx];
        d_zf2[idx] = (o != 0);
    } else if (idx < 1536) {
        int j = idx - 1024;
        unsigned o = 0;
        for (int k = 0; k < 32; k++) o |= d_z3[k * 512 + j];
        d_zf3[j] = (o != 0);
    }
}

// ---------------- layer 1: fp32 GEMM (x[32768,64] x sign(w1)^T[64,2048]) --------
// block: 256 threads, 8 rows x 1024 cols per block (4 col-groups of 256).
// Weight loads double-buffered one k4-step ahead to hide L2 latency.
__global__ __launch_bounds__(256) void l1_kernel(
    const float* __restrict__ x, const float* __restrict__ b1,
    const float* __restrict__ g1, const float* __restrict__ be1,
    const float* __restrict__ m1, const float* __restrict__ v1)
{
    __shared__ __align__(16) float xs[8][64];
    int tid  = threadIdx.x;
    int row0 = blockIdx.y * 8;
    int jb   = blockIdx.x * 1024 + tid;

    for (int i = tid; i < 512; i += 256) xs[i >> 6][i & 63] = x[row0 * 64 + i];
    __syncthreads();

    float acc[4][8];
    #pragma unroll
    for (int g = 0; g < 4; g++)
        #pragma unroll
        for (int r = 0; r < 8; r++) acc[g][r] = 0.f;

    const float4* __restrict__ Wv = (const float4*)d_s1k;
    float4 wc[4], wn[4];
    #pragma unroll
    for (int g = 0; g < 4; g++) wc[g] = Wv[jb + g * 256];

    #pragma unroll 4
    for (int k4 = 0; k4 < 64; k4 += 4) {
        int kn = (k4 + 4 < 64) ? (k4 + 4) : 0;   // last iter reloads k4=0 (discarded)
        #pragma unroll
        for (int g = 0; g < 4; g++)
            wn[g] = Wv[(kn >> 2) * 2048 + jb + g * 256];
        #pragma unroll
        for (int r = 0; r < 8; r++) {
            float4 xv = *(const float4*)&xs[r][k4];
            #pragma unroll
            for (int g = 0; g < 4; g++) {
                acc[g][r] = fmaf(xv.x, wc[g].x, acc[g][r]);
                acc[g][r] = fmaf(xv.y, wc[g].y, acc[g][r]);
                acc[g][r] = fmaf(xv.z, wc[g].z, acc[g][r]);
                acc[g][r] = fmaf(xv.w, wc[g].w, acc[g][r]);
            }
        }
        #pragma unroll
        for (int g = 0; g < 4; g++) wc[g] = wn[g];
    }

    #pragma unroll
    for (int g = 0; g < 4; g++) {
        int j = jb + g * 256;
        float sc  = g1[j] / sqrtf(v1[j] + EPSBN);
        float off = be1[j] - m1[j] * sc;
        float bb  = b1[j];
        #pragma unroll
        for (int r = 0; r < 8; r++) {
            float t = (acc[g][r] + bb) * sc + off;
            unsigned msk = __ballot_sync(0xffffffffu, t > 0.f);
            if ((tid & 31) == 0) d_h1[(row0 + r) * 64 + (j >> 5)] = msk;
        }
    }
}

// ---------------- layer 2: popcount GEMM (2048 -> 1024) ------------------------
// block: 256 threads, each handles 2 output columns (j, j+256), 16 rows per block.
// Weight masks double-buffered one k4-step ahead.
__global__ __launch_bounds__(256) void l2_kernel(
    const float* __restrict__ b2, const float* __restrict__ g2,
    const float* __restrict__ be2, const float* __restrict__ m2,
    const float* __restrict__ v2)
{
    __shared__ __align__(16) unsigned hs[16][64];
    __shared__ int Hrow[16];
    int tid  = threadIdx.x;
    int row0 = blockIdx.y * 16;
    int jb   = blockIdx.x * 512 + tid;    // second column: jb + 256

    for (int i = tid; i < 1024; i += 256) hs[i >> 6][i & 63] = d_h1[row0 * 64 + i];
    __syncthreads();
    if (tid < 16) {
        int s = 0;
        for (int k = 0; k < 64; k++) s += __popc(hs[tid][k]);
        Hrow[tid] = s;
    }
    __syncthreads();

    unsigned a0[16], a1[16];
    #pragma unroll
    for (int r = 0; r < 16; r++) { a0[r] = 0u; a1[r] = 0u; }

    const uint4* __restrict__ Pv = (const uint4*)d_p2v;
    uint4 pc0 = Pv[jb], pc1 = Pv[jb + 256];

    #pragma unroll 2
    for (int k4 = 0; k4 < 64; k4 += 4) {
        int kn = (k4 + 4 < 64) ? (k4 + 4) : 0;
        uint4 pn0 = Pv[(kn >> 2) * 1024 + jb];
        uint4 pn1 = Pv[(kn >> 2) * 1024 + jb + 256];
        #pragma unroll
        for (int r = 0; r < 16; r++) {
            uint4 h = *(const uint4*)&hs[r][k4];
            a0[r] += __popc(h.x & pc0.x) + __popc(h.y & pc0.y) +
                     __popc(h.z & pc0.z) + __popc(h.w & pc0.w);
            a1[r] += __popc(h.x & pc1.x) + __popc(h.y & pc1.y) +
                     __popc(h.z & pc1.z) + __popc(h.w & pc1.w);
        }
        pc0 = pn0; pc1 = pn1;
    }

    #pragma unroll
    for (int g = 0; g < 2; g++) {
        int j = jb + g * 256;
        const unsigned* a = g ? a1 : a0;
        float sc  = g2[j] / sqrtf(v2[j] + EPSBN);
        float off = be2[j] - m2[j] * sc;
        float bb  = b2[j];
        bool  hz  = d_zf2[j] != 0;
        #pragma unroll
        for (int r = 0; r < 16; r++) {
            int v = 2 * (int)a[r] - Hrow[r];
            if (hz) {
                for (int k = 0; k < 64; k++) v += __popc(hs[r][k] & d_z2[k * 1024 + j]);
            }
            float t = ((float)v + bb) * sc + off;
            unsigned msk = __ballot_sync(0xffffffffu, t > 0.f);
            if ((tid & 31) == 0) d_h2[(row0 + r) * 32 + (j >> 5)] = msk;
        }
    }
}

// ---------------- layer 3: popcount GEMM (1024 -> 512) -------------------------
// block: 256 threads, 2 columns per thread (covers all 512), 16 rows per block.
__global__ __launch_bounds__(256) void l3_kernel(
    const float* __restrict__ b3, const float* __restrict__ g3,
    const float* __restrict__ be3, const float* __restrict__ m3,
    const float* __restrict__ v3)
{
    __shared__ __align__(16) unsigned hs[16][32];
    __shared__ int Hrow[16];
    int tid  = threadIdx.x;
    int row0 = blockIdx.x * 16;
    int jb   = tid;                       // second column: tid + 256

    for (int i = tid; i < 512; i += 256) hs[i >> 5][i & 31] = d_h2[row0 * 32 + i];
    __syncthreads();
    if (tid < 16) {
        int s = 0;
        for (int k = 0; k < 32; k++) s += __popc(hs[tid][k]);
        Hrow[tid] = s;
    }
    __syncthreads();

    unsigned a0[16], a1[16];
    #pragma unroll
    for (int r = 0; r < 16; r++) { a0[r] = 0u; a1[r] = 0u; }

    const uint4* __restrict__ Pv = (const uint4*)d_p3v;
    uint4 pc0 = Pv[jb], pc1 = Pv[jb + 256];

    #pragma unroll 2
    for (int k4 = 0; k4 < 32; k4 += 4) {
        int kn = (k4 + 4 < 32) ? (k4 + 4) : 0;
        uint4 pn0 = Pv[(kn >> 2) * 512 + jb];
        uint4 pn1 = Pv[(kn >> 2) * 512 + jb + 256];
        #pragma unroll
        for (int r = 0; r < 16; r++) {
            uint4 h = *(const uint4*)&hs[r][k4];
            a0[r] += __popc(h.x & pc0.x) + __popc(h.y & pc0.y) +
                     __popc(h.z & pc0.z) + __popc(h.w & pc0.w);
            a1[r] += __popc(h.x & pc1.x) + __popc(h.y & pc1.y) +
                     __popc(h.z & pc1.z) + __popc(h.w & pc1.w);
        }
        pc0 = pn0; pc1 = pn1;
    }

    #pragma unroll
    for (int g = 0; g < 2; g++) {
        int j = jb + g * 256;
        const unsigned* a = g ? a1 : a0;
        float sc  = g3[j] / sqrtf(v3[j] + EPSBN);
        float off = be3[j] - m3[j] * sc;
        float bb  = b3[j];
        bool  hz  = d_zf3[j] != 0;
        #pragma unroll
        for (int r = 0; r < 16; r++) {
            int v = 2 * (int)a[r] - Hrow[r];
            if (hz) {
                for (int k = 0; k < 32; k++) v += __popc(hs[r][k] & d_z3[k * 512 + j]);
            }
            float t = ((float)v + bb) * sc + off;
            unsigned msk = __ballot_sync(0xffffffffu, t > 0.f);
            if ((tid & 31) == 0) d_h3[(row0 + r) * 16 + (j >> 5)] = msk;
        }
    }
}

// ---------------- layer 4 + layer 5 + sigmoid (fused) --------------------------
__global__ __launch_bounds__(128) void out_kernel(
    const float* __restrict__ b4, const float* __restrict__ g4,
    const float* __restrict__ be4, const float* __restrict__ m4,
    const float* __restrict__ v4, const float* __restrict__ w5,
    const float* __restrict__ b5, float* __restrict__ out)
{
    __shared__ unsigned p4s[64 * 16], n4s[64 * 16];
    __shared__ float sc4[64], off4[64], bb4[64], w5s[64];
    int tid = threadIdx.x;
    for (int i = tid; i < 1024; i += 128) { p4s[i] = d_p4[i]; n4s[i] = d_n4[i]; }
    if (tid < 64) {
        float sc = g4[tid] / sqrtf(v4[tid] + EPSBN);
        sc4[tid] = sc;
        off4[tid] = be4[tid] - m4[tid] * sc;
        bb4[tid]  = b4[tid];
        w5s[tid]  = w5[tid];
    }
    __syncthreads();

    int row = blockIdx.x * 128 + tid;
    unsigned h[16];
    #pragma unroll
    for (int q = 0; q < 4; q++) {
        uint4 t = *(const uint4*)&d_h3[row * 16 + q * 4];
        h[q * 4] = t.x; h[q * 4 + 1] = t.y; h[q * 4 + 2] = t.z; h[q * 4 + 3] = t.w;
    }

    float z = b5[0];
    #pragma unroll 4
    for (int j = 0; j < 64; j++) {
        int a = 0, bn = 0;
        #pragma unroll
        for (int k = 0; k < 16; k++) {
            a  += __popc(h[k] & p4s[j * 16 + k]);
            bn += __popc(h[k] & n4s[j * 16 + k]);
        }
        float t = ((float)(a - bn) + bb4[j]) * sc4[j] + off4[j];
        if (t > 0.f) z += w5s[j];
    }
    out[row] = 1.f / (1.f + expf(-z));
}

// ---------------- launch ---------------------------------------------------------
extern "C" void kernel_launch(void* const* d_in, const int* in_sizes, int n_in,
                              void* d_out, int out_size) {
    const float* x   = (const float*)d_in[0];
    const float* w1  = (const float*)d_in[1];
    const float* b1  = (const float*)d_in[2];
    const float* w2  = (const float*)d_in[3];
    const float* b2  = (const float*)d_in[4];
    const float* w3  = (const float*)d_in[5];
    const float* b3  = (const float*)d_in[6];
    const float* w4  = (const float*)d_in[7];
    const float* b4  = (const float*)d_in[8];
    const float* w5  = (const float*)d_in[9];
    const float* b5  = (const float*)d_in[10];
    const float* g1  = (const float*)d_in[11];
    const float* be1 = (const float*)d_in[12];
    const float* m1  = (const float*)d_in[13];
    const float* v1  = (const float*)d_in[14];
    const float* g2  = (const float*)d_in[15];
    const float* be2 = (const float*)d_in[16];
    const float* m2  = (const float*)d_in[17];
    const float* v2  = (const float*)d_in[18];
    const float* g3  = (const float*)d_in[19];
    const float* be3 = (const float*)d_in[20];
    const float* m3  = (const float*)d_in[21];
    const float* v3  = (const float*)d_in[22];
    const float* g4  = (const float*)d_in[23];
    const float* be4 = (const float*)d_in[24];
    const float* m4  = (const float*)d_in[25];
    const float* v4  = (const float*)d_in[26];
    float* out = (float*)d_out;

    pack_s1<<<512, 256>>>(w1);
    pack_w<<<324, 256>>>(w2, w3, w4);
    zflags_kernel<<<6, 256>>>();
    l1_kernel<<<dim3(2, 4096), 256>>>(x, b1, g1, be1, m1, v1);
    l2_kernel<<<dim3(2, 2048), 256>>>(b2, g2, be2, m2, v2);
    l3_kernel<<<2048, 256>>>(b3, g3, be3, m3, v3);
    out_kernel<<<256, 128>>>(b4, g4, be4, m4, v4, w5, b5, out);
}

// round 4
// speedup vs baseline: 1.5863x; 1.5863x over previous
#include <cuda_runtime.h>
#include <math.h>
#include <stdint.h>

// Linear_bin: binarized 5-layer MLP, B=32768, 64->2048->1024->512->64->1.
// L1: fp32 FFMA GEMM -> s8 {0,1} activations.
// L2, L3: s8 tensor-core GEMMs (mma.sync.m16n8k32.s8) — exact integer sums.
// L4+L5+sigmoid: fused popcount kernel on bit-packed L3 output.

#define BATCH 32768
#define EPSBN 1e-5f

// ---------------- scratch (static device globals; no allocation) ----------------
__device__ __align__(16) float d_s1k[64 * 2048];     // sign(w1) fp32, k-vectorized
__device__ __align__(16) char  d_w2s[1024 * 2048];   // sign(w2) s8
__device__ __align__(16) char  d_w3s[512 * 1024];    // sign(w3) s8
__device__ unsigned d_p4[64 * 16];
__device__ unsigned d_n4[64 * 16];
__device__ __align__(16) char  d_a1s[BATCH * 2048];  // layer-1 activations {0,1}
__device__ __align__(16) char  d_a2s[BATCH * 1024];  // layer-2 activations {0,1}
__device__ __align__(16) char  d_a3s[BATCH * 512];   // layer-3 activations {0,1}
__device__ __align__(16) unsigned d_h3[BATCH * 16];  // layer-3 bits

// ---------------- helpers --------------------------------------------------------
__device__ __forceinline__ uint32_t smem_u32(const void* p) {
    uint32_t a;
    asm("{ .reg .u64 t; cvta.to.shared.u64 t, %1; cvt.u32.u64 %0, t; }" : "=r"(a) : "l"(p));
    return a;
}
#define LDMX4(r, a) \
    asm volatile("ldmatrix.sync.aligned.m8n8.x4.shared.b16 {%0,%1,%2,%3}, [%4];" \
        : "=r"((r)[0]), "=r"((r)[1]), "=r"((r)[2]), "=r"((r)[3]) : "r"(a))

__device__ __forceinline__ void mma_s8(int* c, const uint32_t* a, uint32_t b0, uint32_t b1) {
    asm volatile(
        "mma.sync.aligned.m16n8k32.row.col.s32.s8.s8.s32 "
        "{%0,%1,%2,%3}, {%4,%5,%6,%7}, {%8,%9}, {%0,%1,%2,%3};"
        : "+r"(c[0]), "+r"(c[1]), "+r"(c[2]), "+r"(c[3])
        : "r"(a[0]), "r"(a[1]), "r"(a[2]), "r"(a[3]), "r"(b0), "r"(b1));
}
__device__ __forceinline__ void cp16(uint32_t dst, const void* src) {
    asm volatile("cp.async.cg.shared.global [%0], [%1], 16;" :: "r"(dst), "l"(src));
}
// conflict-free swizzle for 64-byte rows read by ldmatrix (16B segs)
__device__ __forceinline__ uint32_t swz(int r, int s) {
    return (uint32_t)(r * 64 + ((s ^ ((r >> 1) & 3)) << 4));
}

// ---------------- weight preprocessing -------------------------------------------
__global__ void pack_all(const float* __restrict__ w1, const float* __restrict__ w2,
                         const float* __restrict__ w3, const float* __restrict__ w4) {
    long idx = (long)blockIdx.x * 256 + threadIdx.x;     // 2753536 threads exactly
    if (idx < 131072) {                                  // sign(w1) fp32, k-vectorized
        int j = (int)idx & 2047, k = (int)idx >> 11;
        float v = w1[j * 64 + k];
        d_s1k[((k >> 2) * 2048 + j) * 4 + (k & 3)] = (v > 0.f) ? 1.f : ((v < 0.f) ? -1.f : 0.f);
    } else if (idx < 131072 + 2097152) {                 // sign(w2) s8
        int i = (int)(idx - 131072);
        float v = w2[i];
        d_w2s[i] = (v > 0.f) ? 1 : ((v < 0.f) ? -1 : 0);
    } else if (idx < 131072 + 2097152 + 524288) {        // sign(w3) s8
        int i = (int)(idx - 131072 - 2097152);
        float v = w3[i];
        d_w3s[i] = (v > 0.f) ? 1 : ((v < 0.f) ? -1 : 0);
    } else if (idx < 131072 + 2097152 + 524288 + 1024) { // w4 bitmasks
        int t = (int)(idx - 131072 - 2097152 - 524288);
        int j = t >> 4, w = t & 15;
        unsigned p = 0, n = 0;
        #pragma unroll
        for (int i = 0; i < 32; i++) {
            float v = w4[j * 512 + w * 32 + i];
            if (v > 0.f) p |= (1u << i);
            if (v < 0.f) n |= (1u << i);
        }
        d_p4[j * 16 + w] = p;
        d_n4[j * 16 + w] = n;
    }
}

// ---------------- layer 1: fp32 FFMA GEMM -> s8 {0,1} ----------------------------
// block: 256 threads, 8 rows x 512 cols (2 col-groups) -> ~70 regs, 2x occupancy.
__global__ __launch_bounds__(256) void l1_kernel(
    const float* __restrict__ x, const float* __restrict__ b1,
    const float* __restrict__ g1, const float* __restrict__ be1,
    const float* __restrict__ m1, const float* __restrict__ v1)
{
    __shared__ __align__(16) float xs[8][64];
    int tid  = threadIdx.x;
    int row0 = blockIdx.y * 8;
    int jb   = blockIdx.x * 512 + tid;

    for (int i = tid; i < 512; i += 256) xs[i >> 6][i & 63] = x[row0 * 64 + i];
    __syncthreads();

    float acc[2][8];
    #pragma unroll
    for (int g = 0; g < 2; g++)
        #pragma unroll
        for (int r = 0; r < 8; r++) acc[g][r] = 0.f;

    const float4* __restrict__ Wv = (const float4*)d_s1k;
    #pragma unroll 4
    for (int k4 = 0; k4 < 64; k4 += 4) {
        float4 wv0 = Wv[(k4 >> 2) * 2048 + jb];
        float4 wv1 = Wv[(k4 >> 2) * 2048 + jb + 256];
        #pragma unroll
        for (int r = 0; r < 8; r++) {
            float4 xv = *(const float4*)&xs[r][k4];
            acc[0][r] = fmaf(xv.x, wv0.x, acc[0][r]);
            acc[0][r] = fmaf(xv.y, wv0.y, acc[0][r]);
            acc[0][r] = fmaf(xv.z, wv0.z, acc[0][r]);
            acc[0][r] = fmaf(xv.w, wv0.w, acc[0][r]);
            acc[1][r] = fmaf(xv.x, wv1.x, acc[1][r]);
            acc[1][r] = fmaf(xv.y, wv1.y, acc[1][r]);
            acc[1][r] = fmaf(xv.z, wv1.z, acc[1][r]);
            acc[1][r] = fmaf(xv.w, wv1.w, acc[1][r]);
        }
    }

    #pragma unroll
    for (int g = 0; g < 2; g++) {
        int j = jb + g * 256;
        float sc  = g1[j] / sqrtf(v1[j] + EPSBN);
        float off = be1[j] - m1[j] * sc;
        float bb  = b1[j];
        #pragma unroll
        for (int r = 0; r < 8; r++) {
            float t = (acc[g][r] + bb) * sc + off;
            d_a1s[(size_t)(row0 + r) * 2048 + j] = (t > 0.f) ? 1 : 0;
        }
    }
}

// ---------------- layers 2/3: s8 mma.sync GEMM + BN/threshold --------------------
// CTA: 256 threads (8 warps), tile M=128 x N=128, K in 64-byte chunks,
// cp.async double-buffered, ldmatrix fragment loads, exact s32 accumulation.
template<int LAYER>
__global__ __launch_bounds__(256) void mmas8_kernel(
    const float* __restrict__ bbp, const float* __restrict__ g,
    const float* __restrict__ be, const float* __restrict__ m,
    const float* __restrict__ v)
{
    constexpr int KDIM = (LAYER == 2) ? 2048 : 1024;
    constexpr int NOUT = (LAYER == 2) ? 1024 : 512;
    constexpr int CH   = KDIM / 64;
    const char* __restrict__ A = (LAYER == 2) ? d_a1s : d_a2s;
    const char* __restrict__ W = (LAYER == 2) ? d_w2s : d_w3s;
    char* __restrict__ OUT     = (LAYER == 2) ? d_a2s : d_a3s;

    __shared__ __align__(128) char sA[2][8192];
    __shared__ __align__(128) char sB[2][8192];
    __shared__ float ssc[128], sof[128], sbb[128];

    int tid = threadIdx.x, wid = tid >> 5, lane = tid & 31;
    int N0 = blockIdx.x * 128, R0 = blockIdx.y * 128;
    int warpM = (wid & 3) * 32, warpN = (wid >> 2) * 64;

    // stage loader: A 128x64B + B 128x64B, swizzled, via cp.async
    auto load_stage = [&](int c) {
        int s = c & 1;
        uint32_t ab = smem_u32(sA[s]);
        uint32_t bb = smem_u32(sB[s]);
        const char* Ag = A + (size_t)R0 * KDIM + c * 64;
        const char* Wg = W + (size_t)N0 * KDIM + c * 64;
        #pragma unroll
        for (int i = 0; i < 2; i++) {
            int idx = tid + i * 256;
            int r = idx >> 2, sg = idx & 3;
            cp16(ab + swz(r, sg), Ag + (size_t)r * KDIM + sg * 16);
            cp16(bb + swz(r, sg), Wg + (size_t)r * KDIM + sg * 16);
        }
    };

    load_stage(0);
    asm volatile("cp.async.commit_group;");

    for (int t = tid; t < 128; t += 256) {
        int j = N0 + t;
        float sc = g[j] / sqrtf(v[j] + EPSBN);
        ssc[t] = sc;
        sof[t] = be[j] - m[j] * sc;
        sbb[t] = bbp[j];
    }

    int C_[2][8][4];
    #pragma unroll
    for (int mt = 0; mt < 2; mt++)
        #pragma unroll
        for (int nt = 0; nt < 8; nt++)
            #pragma unroll
            for (int q = 0; q < 4; q++) C_[mt][nt][q] = 0;

    for (int c = 0; c < CH; c++) {
        if (c + 1 < CH) load_stage(c + 1);
        asm volatile("cp.async.commit_group;");
        asm volatile("cp.async.wait_group 1;");
        __syncthreads();

        int s = c & 1;
        uint32_t ab = smem_u32(sA[s]);
        uint32_t bb = smem_u32(sB[s]);

        #pragma unroll
        for (int kk = 0; kk < 2; kk++) {
            uint32_t af[2][4];
            #pragma unroll
            for (int mt = 0; mt < 2; mt++) {
                int row = warpM + mt * 16 + (lane & 7) + ((lane >> 3) & 1) * 8;
                int sg  = kk * 2 + (lane >> 4);
                LDMX4(af[mt], ab + swz(row, sg));
            }
            uint32_t bf[4][4];
            #pragma unroll
            for (int p = 0; p < 4; p++) {
                int row = warpN + p * 16 + (lane & 7) + (lane >> 4) * 8;
                int sg  = kk * 2 + ((lane >> 3) & 1);
                LDMX4(bf[p], bb + swz(row, sg));
            }
            #pragma unroll
            for (int mt = 0; mt < 2; mt++)
                #pragma unroll
                for (int p = 0; p < 4; p++) {
                    mma_s8(C_[mt][2 * p],     af[mt], bf[p][0], bf[p][1]);
                    mma_s8(C_[mt][2 * p + 1], af[mt], bf[p][2], bf[p][3]);
                }
        }
        __syncthreads();
    }

    // epilogue: BN + threshold -> s8 {0,1}
    #pragma unroll
    for (int mt = 0; mt < 2; mt++) {
        #pragma unroll
        for (int nt = 0; nt < 8; nt++) {
            int col = warpN + nt * 8 + (lane & 3) * 2;
            int r0  = R0 + warpM + mt * 16 + (lane >> 2);
            float sc0 = ssc[col],     of0 = sof[col],     bq0 = sbb[col];
            float sc1 = ssc[col + 1], of1 = sof[col + 1], bq1 = sbb[col + 1];
            char2 u;
            u.x = ((((float)C_[mt][nt][0] + bq0) * sc0 + of0) > 0.f) ? 1 : 0;
            u.y = ((((float)C_[mt][nt][1] + bq1) * sc1 + of1) > 0.f) ? 1 : 0;
            *(char2*)&OUT[(size_t)r0 * NOUT + N0 + col] = u;
            u.x = ((((float)C_[mt][nt][2] + bq0) * sc0 + of0) > 0.f) ? 1 : 0;
            u.y = ((((float)C_[mt][nt][3] + bq1) * sc1 + of1) > 0.f) ? 1 : 0;
            *(char2*)&OUT[(size_t)(r0 + 8) * NOUT + N0 + col] = u;
        }
    }
}

// ---------------- bitify layer-3 activations -------------------------------------
__global__ __launch_bounds__(256) void bitify_kernel() {
    int idx = blockIdx.x * 256 + threadIdx.x;            // 524288 threads
    const uint4* p = (const uint4*)d_a3s + (size_t)idx * 2;
    uint4 u0 = p[0], u1 = p[1];
    unsigned vs[8] = {u0.x, u0.y, u0.z, u0.w, u1.x, u1.y, u1.z, u1.w};
    unsigned w = 0;
    #pragma unroll
    for (int i = 0; i < 8; i++)
        w |= (((vs[i] & 0x01010101u) * 0x01020408u) >> 24) << (4 * i);
    d_h3[idx] = w;
}

// ---------------- layer 4 + layer 5 + sigmoid (fused popcount) -------------------
__global__ __launch_bounds__(128) void out_kernel(
    const float* __restrict__ b4, const float* __restrict__ g4,
    const float* __restrict__ be4, const float* __restrict__ m4,
    const float* __restrict__ v4, const float* __restrict__ w5,
    const float* __restrict__ b5, float* __restrict__ out)
{
    __shared__ unsigned p4s[64 * 16], n4s[64 * 16];
    __shared__ float sc4[64], off4[64], bb4[64], w5s[64];
    int tid = threadIdx.x;
    for (int i = tid; i < 1024; i += 128) { p4s[i] = d_p4[i]; n4s[i] = d_n4[i]; }
    if (tid < 64) {
        float sc = g4[tid] / sqrtf(v4[tid] + EPSBN);
        sc4[tid] = sc;
        off4[tid] = be4[tid] - m4[tid] * sc;
        bb4[tid]  = b4[tid];
        w5s[tid]  = w5[tid];
    }
    __syncthreads();

    int row = blockIdx.x * 128 + tid;
    unsigned h[16];
    #pragma unroll
    for (int q = 0; q < 4; q++) {
        uint4 t = *(const uint4*)&d_h3[(size_t)row * 16 + q * 4];
        h[q * 4] = t.x; h[q * 4 + 1] = t.y; h[q * 4 + 2] = t.z; h[q * 4 + 3] = t.w;
    }

    float z = b5[0];
    #pragma unroll 4
    for (int j = 0; j < 64; j++) {
        int a = 0, bn = 0;
        #pragma unroll
        for (int k = 0; k < 16; k++) {
            a  += __popc(h[k] & p4s[j * 16 + k]);
            bn += __popc(h[k] & n4s[j * 16 + k]);
        }
        float t = ((float)(a - bn) + bb4[j]) * sc4[j] + off4[j];
        if (t > 0.f) z += w5s[j];
    }
    out[row] = 1.f / (1.f + expf(-z));
}

// ---------------- launch ---------------------------------------------------------
extern "C" void kernel_launch(void* const* d_in, const int* in_sizes, int n_in,
                              void* d_out, int out_size) {
    const float* x   = (const float*)d_in[0];
    const float* w1  = (const float*)d_in[1];
    const float* b1  = (const float*)d_in[2];
    const float* w2  = (const float*)d_in[3];
    const float* b2  = (const float*)d_in[4];
    const float* w3  = (const float*)d_in[5];
    const float* b3  = (const float*)d_in[6];
    const float* w4  = (const float*)d_in[7];
    const float* b4  = (const float*)d_in[8];
    const float* w5  = (const float*)d_in[9];
    const float* b5  = (const float*)d_in[10];
    const float* g1  = (const float*)d_in[11];
    const float* be1 = (const float*)d_in[12];
    const float* m1  = (const float*)d_in[13];
    const float* v1  = (const float*)d_in[14];
    const float* g2  = (const float*)d_in[15];
    const float* be2 = (const float*)d_in[16];
    const float* m2  = (const float*)d_in[17];
    const float* v2  = (const float*)d_in[18];
    const float* g3  = (const float*)d_in[19];
    const float* be3 = (const float*)d_in[20];
    const float* m3  = (const float*)d_in[21];
    const float* v3  = (const float*)d_in[22];
    const float* g4  = (const float*)d_in[23];
    const float* be4 = (const float*)d_in[24];
    const float* m4  = (const float*)d_in[25];
    const float* v4  = (const float*)d_in[26];
    float* out = (float*)d_out;

    pack_all<<<10756, 256>>>(w1, w2, w3, w4);
    l1_kernel<<<dim3(4, 4096), 256>>>(x, b1, g1, be1, m1, v1);
    mmas8_kernel<2><<<dim3(8, 256), 256>>>(b2, g2, be2, m2, v2);
    mmas8_kernel<3><<<dim3(4, 256), 256>>>(b3, g3, be3, m3, v3);
    bitify_kernel<<<2048, 256>>>();
    out_kernel<<<256, 128>>>(b4, g4, be4, m4, v4, w5, b5, out);
}

// round 5
// speedup vs baseline: 2.1621x; 1.3630x over previous
#include <cuda_runtime.h>
#include <cuda_bf16.h>
#include <math.h>
#include <stdint.h>

// Linear_bin: binarized 5-layer MLP, B=32768, 64->2048->1024->512->64->1.
// L1: bf16 tensor-core GEMM on exact 3-way split of x (fp32-exact products).
// L2, L3: s8 tensor-core GEMMs (mma.m16n8k32.s8), 3-stage cp.async pipeline.
// L4+L5+sigmoid: fused popcount kernel.

#define BATCH 32768
#define EPSBN 1e-5f

// ---------------- scratch (static device globals; no allocation) ----------------
__device__ __align__(16) __nv_bfloat16 d_xp[BATCH * 192];     // x split: hi|mid|lo
__device__ __align__(16) unsigned short d_w1b[2048 * 192];    // sign(w1) bf16, 3x replicated
__device__ __align__(16) char  d_w2s[1024 * 2048];            // sign(w2) s8
__device__ __align__(16) char  d_w3s[512 * 1024];             // sign(w3) s8
__device__ unsigned d_p4[64 * 16];
__device__ unsigned d_n4[64 * 16];
__device__ __align__(16) char  d_a1s[BATCH * 2048];           // layer-1 acts {0,1}
__device__ __align__(16) char  d_a2s[BATCH * 1024];
__device__ __align__(16) char  d_a3s[BATCH * 512];
__device__ __align__(16) unsigned d_h3[BATCH * 16];

// ---------------- helpers --------------------------------------------------------
__device__ __forceinline__ uint32_t smem_u32(const void* p) {
    uint32_t a;
    asm("{ .reg .u64 t; cvta.to.shared.u64 t, %1; cvt.u32.u64 %0, t; }" : "=r"(a) : "l"(p));
    return a;
}
#define LDMX4(r, a) \
    asm volatile("ldmatrix.sync.aligned.m8n8.x4.shared.b16 {%0,%1,%2,%3}, [%4];" \
        : "=r"((r)[0]), "=r"((r)[1]), "=r"((r)[2]), "=r"((r)[3]) : "r"(a))

__device__ __forceinline__ void mma_s8(int* c, const uint32_t* a, uint32_t b0, uint32_t b1) {
    asm volatile(
        "mma.sync.aligned.m16n8k32.row.col.s32.s8.s8.s32 "
        "{%0,%1,%2,%3}, {%4,%5,%6,%7}, {%8,%9}, {%0,%1,%2,%3};"
        : "+r"(c[0]), "+r"(c[1]), "+r"(c[2]), "+r"(c[3])
        : "r"(a[0]), "r"(a[1]), "r"(a[2]), "r"(a[3]), "r"(b0), "r"(b1));
}
__device__ __forceinline__ void mma_bf16(float* c, const uint32_t* a, uint32_t b0, uint32_t b1) {
    asm volatile(
        "mma.sync.aligned.m16n8k16.row.col.f32.bf16.bf16.f32 "
        "{%0,%1,%2,%3}, {%4,%5,%6,%7}, {%8,%9}, {%0,%1,%2,%3};"
        : "+f"(c[0]), "+f"(c[1]), "+f"(c[2]), "+f"(c[3])
        : "r"(a[0]), "r"(a[1]), "r"(a[2]), "r"(a[3]), "r"(b0), "r"(b1));
}
__device__ __forceinline__ void cp16(uint32_t dst, const void* src) {
    asm volatile("cp.async.cg.shared.global [%0], [%1], 16;" :: "r"(dst), "l"(src));
}
// 128-byte rows: XOR low-3 seg bits with row low-3 bits -> conflict-free ldmatrix
__device__ __forceinline__ uint32_t swz128(int r, int s) {
    return (uint32_t)((r << 7) | (((s ^ r) & 7) << 4));
}
// 384-byte rows (K=192 bf16): swizzle within each 128B third
__device__ __forceinline__ uint32_t swz384(int r, int s) {
    return (uint32_t)(r * 384 + (((s & 24) | ((s ^ r) & 7)) << 4));
}

// ---------------- weight preprocessing + x split ---------------------------------
__global__ void pack_all(const float* __restrict__ x,  const float* __restrict__ w1,
                         const float* __restrict__ w2, const float* __restrict__ w3,
                         const float* __restrict__ w4) {
    long idx = (long)blockIdx.x * 256 + threadIdx.x;     // 4850688 threads exactly
    if (idx < 131072) {                                  // sign(w1) bf16, replicated x3
        int n = (int)idx >> 6, k = (int)idx & 63;
        float v = w1[n * 64 + k];
        unsigned short s = (v > 0.f) ? 0x3F80 : ((v < 0.f) ? 0xBF80 : 0);
        d_w1b[n * 192 + k] = s;
        d_w1b[n * 192 + k + 64] = s;
        d_w1b[n * 192 + k + 128] = s;
    } else if (idx < 131072 + 2097152) {                 // x 3-way exact bf16 split
        int i = (int)(idx - 131072);
        int row = i >> 6, k = i & 63;
        float v = x[i];
        __nv_bfloat16 hi = __float2bfloat16(v);
        float r1 = v - __bfloat162float(hi);
        __nv_bfloat16 mid = __float2bfloat16(r1);
        float r2 = r1 - __bfloat162float(mid);
        __nv_bfloat16 lo = __float2bfloat16(r2);
        d_xp[(size_t)row * 192 + k]       = hi;
        d_xp[(size_t)row * 192 + k + 64]  = mid;
        d_xp[(size_t)row * 192 + k + 128] = lo;
    } else if (idx < 131072 + 2097152 + 2097152) {       // sign(w2) s8
        int i = (int)(idx - 131072 - 2097152);
        float v = w2[i];
        d_w2s[i] = (v > 0.f) ? 1 : ((v < 0.f) ? -1 : 0);
    } else if (idx < 131072 + 2097152 + 2097152 + 524288) { // sign(w3) s8
        int i = (int)(idx - 131072 - 2097152 - 2097152);
        float v = w3[i];
        d_w3s[i] = (v > 0.f) ? 1 : ((v < 0.f) ? -1 : 0);
    } else if (idx < 131072 + 2097152 + 2097152 + 524288 + 1024) { // w4 bitmasks
        int t = (int)(idx - 131072 - 2097152 - 2097152 - 524288);
        int j = t >> 4, w = t & 15;
        unsigned p = 0, n = 0;
        #pragma unroll
        for (int i = 0; i < 32; i++) {
            float v = w4[j * 512 + w * 32 + i];
            if (v > 0.f) p |= (1u << i);
            if (v < 0.f) n |= (1u << i);
        }
        d_p4[j * 16 + w] = p;
        d_n4[j * 16 + w] = n;
    }
}

// ---------------- layer 1: bf16 mma GEMM (M=32768, N=2048, K=192) ----------------
// CTA tile 128x128, K fully resident. Dynamic smem: A 48K + B 48K + BN 1.5K.
#define L1_SMEM (49152 + 49152 + 3 * 512)
__global__ __launch_bounds__(256) void l1mma_kernel(
    const float* __restrict__ b1, const float* __restrict__ g1,
    const float* __restrict__ be1, const float* __restrict__ m1,
    const float* __restrict__ v1)
{
    extern __shared__ __align__(128) char smem[];
    uint32_t sb = smem_u32(smem);
    float* ssc = (float*)(smem + 98304);
    float* sof = (float*)(smem + 98816);
    float* sbb = (float*)(smem + 99328);

    int tid = threadIdx.x, wid = tid >> 5, lane = tid & 31;
    int N0 = blockIdx.x * 128, R0 = blockIdx.y * 128;
    int warpM = (wid & 3) * 32, warpN = (wid >> 2) * 64;
    uint32_t ab = sb, bb = sb + 49152;

    const char* Ag = (const char*)(d_xp + (size_t)R0 * 192);
    const char* Wg = (const char*)(d_w1b + (size_t)N0 * 192);
    #pragma unroll
    for (int i = 0; i < 12; i++) {
        int idx = tid + i * 256;        // 3072 x 16B each for A and B
        int r = idx / 24, sg = idx % 24;
        cp16(ab + swz384(r, sg), Ag + (size_t)r * 384 + sg * 16);
        cp16(bb + swz384(r, sg), Wg + (size_t)r * 384 + sg * 16);
    }
    asm volatile("cp.async.commit_group;");

    for (int t = tid; t < 128; t += 256) {
        int j = N0 + t;
        float sc = g1[j] / sqrtf(v1[j] + EPSBN);
        ssc[t] = sc;
        sof[t] = be1[j] - m1[j] * sc;
        sbb[t] = b1[j];
    }
    float C_[2][8][4];
    #pragma unroll
    for (int mt = 0; mt < 2; mt++)
        #pragma unroll
        for (int nt = 0; nt < 8; nt++)
            #pragma unroll
            for (int q = 0; q < 4; q++) C_[mt][nt][q] = 0.f;

    asm volatile("cp.async.wait_group 0;");
    __syncthreads();

    #pragma unroll
    for (int ks = 0; ks < 12; ks++) {   // k16 steps
        uint32_t af[2][4];
        #pragma unroll
        for (int mt = 0; mt < 2; mt++) {
            int row = warpM + mt * 16 + (lane & 7) + ((lane >> 3) & 1) * 8;
            int sg  = ks * 2 + (lane >> 4);
            LDMX4(af[mt], ab + swz384(row, sg));
        }
        uint32_t bf[4][4];
        #pragma unroll
        for (int p = 0; p < 4; p++) {
            int row = warpN + p * 16 + (lane & 7) + (lane >> 4) * 8;
            int sg  = ks * 2 + ((lane >> 3) & 1);
            LDMX4(bf[p], bb + swz384(row, sg));
        }
        #pragma unroll
        for (int mt = 0; mt < 2; mt++)
            #pragma unroll
            for (int p = 0; p < 4; p++) {
                mma_bf16(C_[mt][2 * p],     af[mt], bf[p][0], bf[p][1]);
                mma_bf16(C_[mt][2 * p + 1], af[mt], bf[p][2], bf[p][3]);
            }
    }

    #pragma unroll
    for (int mt = 0; mt < 2; mt++)
        #pragma unroll
        for (int nt = 0; nt < 8; nt++) {
            int col = warpN + nt * 8 + (lane & 3) * 2;
            int r0  = R0 + warpM + mt * 16 + (lane >> 2);
            float sc0 = ssc[col],     of0 = sof[col],     bq0 = sbb[col];
            float sc1 = ssc[col + 1], of1 = sof[col + 1], bq1 = sbb[col + 1];
            char2 u;
            u.x = (((C_[mt][nt][0] + bq0) * sc0 + of0) > 0.f) ? 1 : 0;
            u.y = (((C_[mt][nt][1] + bq1) * sc1 + of1) > 0.f) ? 1 : 0;
            *(char2*)&d_a1s[(size_t)r0 * 2048 + N0 + col] = u;
            u.x = (((C_[mt][nt][2] + bq0) * sc0 + of0) > 0.f) ? 1 : 0;
            u.y = (((C_[mt][nt][3] + bq1) * sc1 + of1) > 0.f) ? 1 : 0;
            *(char2*)&d_a1s[(size_t)(r0 + 8) * 2048 + N0 + col] = u;
        }
}

// ---------------- layers 2/3: s8 mma GEMM, tile 128x256, 3-stage pipeline --------
// Dynamic smem: 3 x (A 16K + B 32K) + BN 3K = 150528 B.
#define MMAS8_SMEM 150528
template<int LAYER>
__global__ __launch_bounds__(256) void mmas8_kernel(
    const float* __restrict__ bbp, const float* __restrict__ g,
    const float* __restrict__ be, const float* __restrict__ m,
    const float* __restrict__ v)
{
    constexpr int KDIM = (LAYER == 2) ? 2048 : 1024;
    constexpr int NOUT = (LAYER == 2) ? 1024 : 512;
    constexpr int CH   = KDIM / 128;
    const char* __restrict__ A = (LAYER == 2) ? d_a1s : d_a2s;
    const char* __restrict__ W = (LAYER == 2) ? d_w2s : d_w3s;
    char* __restrict__ OUT     = (LAYER == 2) ? d_a2s : d_a3s;

    extern __shared__ __align__(128) char smem[];
    uint32_t sb = smem_u32(smem);
    float* ssc = (float*)(smem + 147456);
    float* sof = (float*)(smem + 148480);
    float* sbb = (float*)(smem + 149504);

    int tid = threadIdx.x, wid = tid >> 5, lane = tid & 31;
    int N0 = blockIdx.x * 256, R0 = blockIdx.y * 128;
    int warpM = (wid & 3) * 32, warpN = (wid >> 2) * 128;

    auto load_stage = [&](int c) {
        int s3 = c % 3;
        uint32_t ab = sb + s3 * 16384;
        uint32_t bbs = sb + 49152 + s3 * 32768;
        const char* Ag = A + (size_t)R0 * KDIM + c * 128;
        const char* Wg = W + (size_t)N0 * KDIM + c * 128;
        #pragma unroll
        for (int i = 0; i < 4; i++) {                  // A: 128 rows x 8 segs
            int idx = tid + i * 256;
            int r = idx >> 3, sg = idx & 7;
            cp16(ab + swz128(r, sg), Ag + (size_t)r * KDIM + sg * 16);
        }
        #pragma unroll
        for (int i = 0; i < 8; i++) {                  // B: 256 rows x 8 segs
            int idx = tid + i * 256;
            int r = idx >> 3, sg = idx & 7;
            cp16(bbs + swz128(r, sg), Wg + (size_t)r * KDIM + sg * 16);
        }
        asm volatile("cp.async.commit_group;");
    };

    load_stage(0);
    load_stage(1);

    for (int t = tid; t < 256; t += 256) {
        int j = N0 + t;
        float sc = g[j] / sqrtf(v[j] + EPSBN);
        ssc[t] = sc;
        sof[t] = be[j] - m[j] * sc;
        sbb[t] = bbp[j];
    }

    int C_[2][16][4];
    #pragma unroll
    for (int mt = 0; mt < 2; mt++)
        #pragma unroll
        for (int nt = 0; nt < 16; nt++)
            #pragma unroll
            for (int q = 0; q < 4; q++) C_[mt][nt][q] = 0;

    for (int c = 0; c < CH; c++) {
        asm volatile("cp.async.wait_group 1;");
        __syncthreads();
        if (c + 2 < CH) load_stage(c + 2);

        int s3 = c % 3;
        uint32_t ab = sb + s3 * 16384;
        uint32_t bbs = sb + 49152 + s3 * 32768;

        #pragma unroll
        for (int kk = 0; kk < 4; kk++) {               // 32B k-steps
            uint32_t af[2][4];
            #pragma unroll
            for (int mt = 0; mt < 2; mt++) {
                int row = warpM + mt * 16 + (lane & 7) + ((lane >> 3) & 1) * 8;
                int sg  = kk * 2 + (lane >> 4);
                LDMX4(af[mt], ab + swz128(row, sg));
            }
            #pragma unroll
            for (int ng = 0; ng < 2; ng++) {
                uint32_t bf[4][4];
                #pragma unroll
                for (int p = 0; p < 4; p++) {
                    int row = warpN + ng * 64 + p * 16 + (lane & 7) + (lane >> 4) * 8;
                    int sg  = kk * 2 + ((lane >> 3) & 1);
                    LDMX4(bf[p], bbs + swz128(row, sg));
                }
                #pragma unroll
                for (int mt = 0; mt < 2; mt++)
                    #pragma unroll
                    for (int p = 0; p < 4; p++) {
                        mma_s8(C_[mt][ng * 8 + 2 * p],     af[mt], bf[p][0], bf[p][1]);
                        mma_s8(C_[mt][ng * 8 + 2 * p + 1], af[mt], bf[p][2], bf[p][3]);
                    }
            }
        }
    }

    // epilogue: BN + threshold -> s8 {0,1}
    #pragma unroll
    for (int mt = 0; mt < 2; mt++)
        #pragma unroll
        for (int nt = 0; nt < 16; nt++) {
            int col = warpN + nt * 8 + (lane & 3) * 2;
            int r0  = R0 + warpM + mt * 16 + (lane >> 2);
            float sc0 = ssc[col],     of0 = sof[col],     bq0 = sbb[col];
            float sc1 = ssc[col + 1], of1 = sof[col + 1], bq1 = sbb[col + 1];
            char2 u;
            u.x = ((((float)C_[mt][nt][0] + bq0) * sc0 + of0) > 0.f) ? 1 : 0;
            u.y = ((((float)C_[mt][nt][1] + bq1) * sc1 + of1) > 0.f) ? 1 : 0;
            *(char2*)&OUT[(size_t)r0 * NOUT + N0 + col] = u;
            u.x = ((((float)C_[mt][nt][2] + bq0) * sc0 + of0) > 0.f) ? 1 : 0;
            u.y = ((((float)C_[mt][nt][3] + bq1) * sc1 + of1) > 0.f) ? 1 : 0;
            *(char2*)&OUT[(size_t)(r0 + 8) * NOUT + N0 + col] = u;
        }
}

// ---------------- bitify layer-3 activations -------------------------------------
__global__ __launch_bounds__(256) void bitify_kernel() {
    int idx = blockIdx.x * 256 + threadIdx.x;            // 524288 threads
    const uint4* p = (const uint4*)d_a3s + (size_t)idx * 2;
    uint4 u0 = p[0], u1 = p[1];
    unsigned vs[8] = {u0.x, u0.y, u0.z, u0.w, u1.x, u1.y, u1.z, u1.w};
    unsigned w = 0;
    #pragma unroll
    for (int i = 0; i < 8; i++)
        w |= (((vs[i] & 0x01010101u) * 0x01020408u) >> 24) << (4 * i);
    d_h3[idx] = w;
}

// ---------------- layer 4 + layer 5 + sigmoid (fused popcount) -------------------
__global__ __launch_bounds__(128) void out_kernel(
    const float* __restrict__ b4, const float* __restrict__ g4,
    const float* __restrict__ be4, const float* __restrict__ m4,
    const float* __restrict__ v4, const float* __restrict__ w5,
    const float* __restrict__ b5, float* __restrict__ out)
{
    __shared__ unsigned p4s[64 * 16], n4s[64 * 16];
    __shared__ float sc4[64], off4[64], bb4[64], w5s[64];
    int tid = threadIdx.x;
    for (int i = tid; i < 1024; i += 128) { p4s[i] = d_p4[i]; n4s[i] = d_n4[i]; }
    if (tid < 64) {
        float sc = g4[tid] / sqrtf(v4[tid] + EPSBN);
        sc4[tid] = sc;
        off4[tid] = be4[tid] - m4[tid] * sc;
        bb4[tid]  = b4[tid];
        w5s[tid]  = w5[tid];
    }
    __syncthreads();

    int row = blockIdx.x * 128 + tid;
    unsigned h[16];
    #pragma unroll
    for (int q = 0; q < 4; q++) {
        uint4 t = *(const uint4*)&d_h3[(size_t)row * 16 + q * 4];
        h[q * 4] = t.x; h[q * 4 + 1] = t.y; h[q * 4 + 2] = t.z; h[q * 4 + 3] = t.w;
    }

    float z = b5[0];
    #pragma unroll 4
    for (int j = 0; j < 64; j++) {
        int a = 0, bn = 0;
        #pragma unroll
        for (int k = 0; k < 16; k++) {
            a  += __popc(h[k] & p4s[j * 16 + k]);
            bn += __popc(h[k] & n4s[j * 16 + k]);
        }
        float t = ((float)(a - bn) + bb4[j]) * sc4[j] + off4[j];
        if (t > 0.f) z += w5s[j];
    }
    out[row] = 1.f / (1.f + expf(-z));
}

// ---------------- launch ---------------------------------------------------------
extern "C" void kernel_launch(void* const* d_in, const int* in_sizes, int n_in,
                              void* d_out, int out_size) {
    const float* x   = (const float*)d_in[0];
    const float* w1  = (const float*)d_in[1];
    const float* b1  = (const float*)d_in[2];
    const float* w2  = (const float*)d_in[3];
    const float* b2  = (const float*)d_in[4];
    const float* w3  = (const float*)d_in[5];
    const float* b3  = (const float*)d_in[6];
    const float* w4  = (const float*)d_in[7];
    const float* b4  = (const float*)d_in[8];
    const float* w5  = (const float*)d_in[9];
    const float* b5  = (const float*)d_in[10];
    const float* g1  = (const float*)d_in[11];
    const float* be1 = (const float*)d_in[12];
    const float* m1  = (const float*)d_in[13];
    const float* v1  = (const float*)d_in[14];
    const float* g2  = (const float*)d_in[15];
    const float* be2 = (const float*)d_in[16];
    const float* m2  = (const float*)d_in[17];
    const float* v2  = (const float*)d_in[18];
    const float* g3  = (const float*)d_in[19];
    const float* be3 = (const float*)d_in[20];
    const float* m3  = (const float*)d_in[21];
    const float* v3  = (const float*)d_in[22];
    const float* g4  = (const float*)d_in[23];
    const float* be4 = (const float*)d_in[24];
    const float* m4  = (const float*)d_in[25];
    const float* v4  = (const float*)d_in[26];
    float* out = (float*)d_out;

    cudaFuncSetAttribute(l1mma_kernel, cudaFuncAttributeMaxDynamicSharedMemorySize, L1_SMEM);
    cudaFuncSetAttribute(mmas8_kernel<2>, cudaFuncAttributeMaxDynamicSharedMemorySize, MMAS8_SMEM);
    cudaFuncSetAttribute(mmas8_kernel<3>, cudaFuncAttributeMaxDynamicSharedMemorySize, MMAS8_SMEM);

    pack_all<<<18948, 256>>>(x, w1, w2, w3, w4);
    l1mma_kernel<<<dim3(16, 256), 256, L1_SMEM>>>(b1, g1, be1, m1, v1);
    mmas8_kernel<2><<<dim3(4, 256), 256, MMAS8_SMEM>>>(b2, g2, be2, m2, v2);
    mmas8_kernel<3><<<dim3(2, 256), 256, MMAS8_SMEM>>>(b3, g3, be3, m3, v3);
    bitify_kernel<<<2048, 256>>>();
    out_kernel<<<256, 128>>>(b4, g4, be4, m4, v4, w5, b5, out);
}

// round 6
// speedup vs baseline: 2.2816x; 1.0552x over previous
#include <cuda_runtime.h>
#include <cuda_bf16.h>
#include <math.h>
#include <stdint.h>

// Linear_bin: binarized 5-layer MLP, B=32768, 64->2048->1024->512->64->1.
// L1: bf16 tensor-core GEMM on exact 3-way split of x.
// L2, L3: s8 tensor-core GEMMs (mma.m16n8k32.s8), 3-stage cp.async pipeline,
//         tile 128x128, 2 CTAs/SM.
// L4+L5+sigmoid: fused popcount kernel.

#define BATCH 32768
#define EPSBN 1e-5f

// ---------------- scratch (static device globals; no allocation) ----------------
__device__ __align__(16) __nv_bfloat16 d_xp[BATCH * 192];     // x split: hi|mid|lo
__device__ __align__(16) unsigned short d_w1b[2048 * 192];    // sign(w1) bf16, 3x replicated
__device__ __align__(16) char  d_w2s[1024 * 2048];            // sign(w2) s8
__device__ __align__(16) char  d_w3s[512 * 1024];             // sign(w3) s8
__device__ unsigned d_p4[64 * 16];
__device__ unsigned d_n4[64 * 16];
__device__ __align__(16) char  d_a1s[BATCH * 2048];           // layer-1 acts {0,1}
__device__ __align__(16) char  d_a2s[BATCH * 1024];
__device__ __align__(16) char  d_a3s[BATCH * 512];
__device__ __align__(16) unsigned d_h3[BATCH * 16];

// ---------------- helpers --------------------------------------------------------
__device__ __forceinline__ uint32_t smem_u32(const void* p) {
    uint32_t a;
    asm("{ .reg .u64 t; cvta.to.shared.u64 t, %1; cvt.u32.u64 %0, t; }" : "=r"(a) : "l"(p));
    return a;
}
#define LDMX4(r, a) \
    asm volatile("ldmatrix.sync.aligned.m8n8.x4.shared.b16 {%0,%1,%2,%3}, [%4];" \
        : "=r"((r)[0]), "=r"((r)[1]), "=r"((r)[2]), "=r"((r)[3]) : "r"(a))

__device__ __forceinline__ void mma_s8(int* c, const uint32_t* a, uint32_t b0, uint32_t b1) {
    asm volatile(
        "mma.sync.aligned.m16n8k32.row.col.s32.s8.s8.s32 "
        "{%0,%1,%2,%3}, {%4,%5,%6,%7}, {%8,%9}, {%0,%1,%2,%3};"
        : "+r"(c[0]), "+r"(c[1]), "+r"(c[2]), "+r"(c[3])
        : "r"(a[0]), "r"(a[1]), "r"(a[2]), "r"(a[3]), "r"(b0), "r"(b1));
}
__device__ __forceinline__ void mma_bf16(float* c, const uint32_t* a, uint32_t b0, uint32_t b1) {
    asm volatile(
        "mma.sync.aligned.m16n8k16.row.col.f32.bf16.bf16.f32 "
        "{%0,%1,%2,%3}, {%4,%5,%6,%7}, {%8,%9}, {%0,%1,%2,%3};"
        : "+f"(c[0]), "+f"(c[1]), "+f"(c[2]), "+f"(c[3])
        : "r"(a[0]), "r"(a[1]), "r"(a[2]), "r"(a[3]), "r"(b0), "r"(b1));
}
__device__ __forceinline__ void cp16(uint32_t dst, const void* src) {
    asm volatile("cp.async.cg.shared.global [%0], [%1], 16;" :: "r"(dst), "l"(src));
}
// 128-byte rows: XOR low-3 seg bits with row low-3 bits -> conflict-free ldmatrix
__device__ __forceinline__ uint32_t swz128(int r, int s) {
    return (uint32_t)((r << 7) | (((s ^ r) & 7) << 4));
}
// 384-byte rows (K=192 bf16): swizzle within each 128B third
__device__ __forceinline__ uint32_t swz384(int r, int s) {
    return (uint32_t)(r * 384 + (((s & 24) | ((s ^ r) & 7)) << 4));
}

// ---------------- weight preprocessing + x split ---------------------------------
__global__ void pack_all(const float* __restrict__ x,  const float* __restrict__ w1,
                         const float* __restrict__ w2, const float* __restrict__ w3,
                         const float* __restrict__ w4) {
    long idx = (long)blockIdx.x * 256 + threadIdx.x;     // 4850688 threads exactly
    if (idx < 131072) {                                  // sign(w1) bf16, replicated x3
        int n = (int)idx >> 6, k = (int)idx & 63;
        float v = w1[n * 64 + k];
        unsigned short s = (v > 0.f) ? 0x3F80 : ((v < 0.f) ? 0xBF80 : 0);
        d_w1b[n * 192 + k] = s;
        d_w1b[n * 192 + k + 64] = s;
        d_w1b[n * 192 + k + 128] = s;
    } else if (idx < 131072 + 2097152) {                 // x 3-way exact bf16 split
        int i = (int)(idx - 131072);
        int row = i >> 6, k = i & 63;
        float v = x[i];
        __nv_bfloat16 hi = __float2bfloat16(v);
        float r1 = v - __bfloat162float(hi);
        __nv_bfloat16 mid = __float2bfloat16(r1);
        float r2 = r1 - __bfloat162float(mid);
        __nv_bfloat16 lo = __float2bfloat16(r2);
        d_xp[(size_t)row * 192 + k]       = hi;
        d_xp[(size_t)row * 192 + k + 64]  = mid;
        d_xp[(size_t)row * 192 + k + 128] = lo;
    } else if (idx < 131072 + 2097152 + 2097152) {       // sign(w2) s8
        int i = (int)(idx - 131072 - 2097152);
        float v = w2[i];
        d_w2s[i] = (v > 0.f) ? 1 : ((v < 0.f) ? -1 : 0);
    } else if (idx < 131072 + 2097152 + 2097152 + 524288) { // sign(w3) s8
        int i = (int)(idx - 131072 - 2097152 - 2097152);
        float v = w3[i];
        d_w3s[i] = (v > 0.f) ? 1 : ((v < 0.f) ? -1 : 0);
    } else if (idx < 131072 + 2097152 + 2097152 + 524288 + 1024) { // w4 bitmasks
        int t = (int)(idx - 131072 - 2097152 - 2097152 - 524288);
        int j = t >> 4, w = t & 15;
        unsigned p = 0, n = 0;
        #pragma unroll
        for (int i = 0; i < 32; i++) {
            float v = w4[j * 512 + w * 32 + i];
            if (v > 0.f) p |= (1u << i);
            if (v < 0.f) n |= (1u << i);
        }
        d_p4[j * 16 + w] = p;
        d_n4[j * 16 + w] = n;
    }
}

// ---------------- layer 1: bf16 mma GEMM (M=32768, N=2048, K=192) ----------------
// CTA tile 128x128, K fully resident. Dynamic smem: A 48K + B 48K + BN 1.5K.
#define L1_SMEM (49152 + 49152 + 3 * 512)
__global__ __launch_bounds__(256, 2) void l1mma_kernel(
    const float* __restrict__ b1, const float* __restrict__ g1,
    const float* __restrict__ be1, const float* __restrict__ m1,
    const float* __restrict__ v1)
{
    extern __shared__ __align__(128) char smem[];
    uint32_t sb = smem_u32(smem);
    float* ssc = (float*)(smem + 98304);
    float* sof = (float*)(smem + 98816);
    float* sbb = (float*)(smem + 99328);

    int tid = threadIdx.x, wid = tid >> 5, lane = tid & 31;
    int N0 = blockIdx.x * 128, R0 = blockIdx.y * 128;
    int warpM = (wid & 3) * 32, warpN = (wid >> 2) * 64;
    uint32_t ab = sb, bb = sb + 49152;

    const char* Ag = (const char*)(d_xp + (size_t)R0 * 192);
    const char* Wg = (const char*)(d_w1b + (size_t)N0 * 192);
    #pragma unroll
    for (int i = 0; i < 12; i++) {
        int idx = tid + i * 256;        // 3072 x 16B each for A and B
        int r = idx / 24, sg = idx % 24;
        cp16(ab + swz384(r, sg), Ag + (size_t)r * 384 + sg * 16);
        cp16(bb + swz384(r, sg), Wg + (size_t)r * 384 + sg * 16);
    }
    asm volatile("cp.async.commit_group;");

    for (int t = tid; t < 128; t += 256) {
        int j = N0 + t;
        float sc = g1[j] / sqrtf(v1[j] + EPSBN);
        ssc[t] = sc;
        sof[t] = be1[j] - m1[j] * sc;
        sbb[t] = b1[j];
    }
    float C_[2][8][4];
    #pragma unroll
    for (int mt = 0; mt < 2; mt++)
        #pragma unroll
        for (int nt = 0; nt < 8; nt++)
            #pragma unroll
            for (int q = 0; q < 4; q++) C_[mt][nt][q] = 0.f;

    asm volatile("cp.async.wait_group 0;");
    __syncthreads();

    #pragma unroll
    for (int ks = 0; ks < 12; ks++) {   // k16 steps
        uint32_t af[2][4];
        #pragma unroll
        for (int mt = 0; mt < 2; mt++) {
            int row = warpM + mt * 16 + (lane & 7) + ((lane >> 3) & 1) * 8;
            int sg  = ks * 2 + (lane >> 4);
            LDMX4(af[mt], ab + swz384(row, sg));
        }
        uint32_t bf[4][4];
        #pragma unroll
        for (int p = 0; p < 4; p++) {
            int row = warpN + p * 16 + (lane & 7) + (lane >> 4) * 8;
            int sg  = ks * 2 + ((lane >> 3) & 1);
            LDMX4(bf[p], bb + swz384(row, sg));
        }
        #pragma unroll
        for (int mt = 0; mt < 2; mt++)
            #pragma unroll
            for (int p = 0; p < 4; p++) {
                mma_bf16(C_[mt][2 * p],     af[mt], bf[p][0], bf[p][1]);
                mma_bf16(C_[mt][2 * p + 1], af[mt], bf[p][2], bf[p][3]);
            }
    }

    #pragma unroll
    for (int mt = 0; mt < 2; mt++)
        #pragma unroll
        for (int nt = 0; nt < 8; nt++) {
            int col = warpN + nt * 8 + (lane & 3) * 2;
            int r0  = R0 + warpM + mt * 16 + (lane >> 2);
            float sc0 = ssc[col],     of0 = sof[col],     bq0 = sbb[col];
            float sc1 = ssc[col + 1], of1 = sof[col + 1], bq1 = sbb[col + 1];
            char2 u;
            u.x = (((C_[mt][nt][0] + bq0) * sc0 + of0) > 0.f) ? 1 : 0;
            u.y = (((C_[mt][nt][1] + bq1) * sc1 + of1) > 0.f) ? 1 : 0;
            *(char2*)&d_a1s[(size_t)r0 * 2048 + N0 + col] = u;
            u.x = (((C_[mt][nt][2] + bq0) * sc0 + of0) > 0.f) ? 1 : 0;
            u.y = (((C_[mt][nt][3] + bq1) * sc1 + of1) > 0.f) ? 1 : 0;
            *(char2*)&d_a1s[(size_t)(r0 + 8) * 2048 + N0 + col] = u;
        }
}

// ---------------- layers 2/3: s8 mma GEMM, tile 128x128, 3-stage, 2 CTA/SM -------
// Dynamic smem: 3 x (A 16K + B 16K) + BN 1.5K = 99840 B -> 2 CTAs/SM.
#define MMAS8_SMEM 99840
template<int LAYER>
__global__ __launch_bounds__(256, 2) void mmas8_kernel(
    const float* __restrict__ bbp, const float* __restrict__ g,
    const float* __restrict__ be, const float* __restrict__ m,
    const float* __restrict__ v)
{
    constexpr int KDIM = (LAYER == 2) ? 2048 : 1024;
    constexpr int NOUT = (LAYER == 2) ? 1024 : 512;
    constexpr int CH   = KDIM / 128;
    const char* __restrict__ A = (LAYER == 2) ? d_a1s : d_a2s;
    const char* __restrict__ W = (LAYER == 2) ? d_w2s : d_w3s;
    char* __restrict__ OUT     = (LAYER == 2) ? d_a2s : d_a3s;

    extern __shared__ __align__(128) char smem[];
    uint32_t sb = smem_u32(smem);
    float* ssc = (float*)(smem + 98304);
    float* sof = (float*)(smem + 98816);
    float* sbb = (float*)(smem + 99328);

    int tid = threadIdx.x, wid = tid >> 5, lane = tid & 31;
    int N0 = blockIdx.x * 128, R0 = blockIdx.y * 128;
    int warpM = (wid & 3) * 32, warpN = (wid >> 2) * 64;

    auto load_stage = [&](int c) {
        int s3 = c % 3;
        uint32_t ab  = sb + s3 * 16384;
        uint32_t bbs = sb + 49152 + s3 * 16384;
        const char* Ag = A + (size_t)R0 * KDIM + c * 128;
        const char* Wg = W + (size_t)N0 * KDIM + c * 128;
        #pragma unroll
        for (int i = 0; i < 4; i++) {                  // A: 128 rows x 8 segs
            int idx = tid + i * 256;
            int r = idx >> 3, sg = idx & 7;
            cp16(ab + swz128(r, sg), Ag + (size_t)r * KDIM + sg * 16);
        }
        #pragma unroll
        for (int i = 0; i < 4; i++) {                  // B: 128 rows x 8 segs
            int idx = tid + i * 256;
            int r = idx >> 3, sg = idx & 7;
            cp16(bbs + swz128(r, sg), Wg + (size_t)r * KDIM + sg * 16);
        }
        asm volatile("cp.async.commit_group;");
    };

    load_stage(0);
    load_stage(1);

    for (int t = tid; t < 128; t += 256) {
        int j = N0 + t;
        float sc = g[j] / sqrtf(v[j] + EPSBN);
        ssc[t] = sc;
        sof[t] = be[j] - m[j] * sc;
        sbb[t] = bbp[j];
    }

    int C_[2][8][4];
    #pragma unroll
    for (int mt = 0; mt < 2; mt++)
        #pragma unroll
        for (int nt = 0; nt < 8; nt++)
            #pragma unroll
            for (int q = 0; q < 4; q++) C_[mt][nt][q] = 0;

    for (int c = 0; c < CH; c++) {
        asm volatile("cp.async.wait_group 1;");
        __syncthreads();
        if (c + 2 < CH) load_stage(c + 2);

        int s3 = c % 3;
        uint32_t ab  = sb + s3 * 16384;
        uint32_t bbs = sb + 49152 + s3 * 16384;

        #pragma unroll
        for (int kk = 0; kk < 4; kk++) {               // 32B k-steps
            uint32_t af[2][4];
            #pragma unroll
            for (int mt = 0; mt < 2; mt++) {
                int row = warpM + mt * 16 + (lane & 7) + ((lane >> 3) & 1) * 8;
                int sg  = kk * 2 + (lane >> 4);
                LDMX4(af[mt], ab + swz128(row, sg));
            }
            uint32_t bf[4][4];
            #pragma unroll
            for (int p = 0; p < 4; p++) {
                int row = warpN + p * 16 + (lane & 7) + (lane >> 4) * 8;
                int sg  = kk * 2 + ((lane >> 3) & 1);
                LDMX4(bf[p], bbs + swz128(row, sg));
            }
            #pragma unroll
            for (int mt = 0; mt < 2; mt++)
                #pragma unroll
                for (int p = 0; p < 4; p++) {
                    mma_s8(C_[mt][2 * p],     af[mt], bf[p][0], bf[p][1]);
                    mma_s8(C_[mt][2 * p + 1], af[mt], bf[p][2], bf[p][3]);
                }
        }
    }

    // epilogue: BN + threshold -> s8 {0,1}
    #pragma unroll
    for (int mt = 0; mt < 2; mt++)
        #pragma unroll
        for (int nt = 0; nt < 8; nt++) {
            int col = warpN + nt * 8 + (lane & 3) * 2;
            int r0  = R0 + warpM + mt * 16 + (lane >> 2);
            float sc0 = ssc[col],     of0 = sof[col],     bq0 = sbb[col];
            float sc1 = ssc[col + 1], of1 = sof[col + 1], bq1 = sbb[col + 1];
            char2 u;
            u.x = ((((float)C_[mt][nt][0] + bq0) * sc0 + of0) > 0.f) ? 1 : 0;
            u.y = ((((float)C_[mt][nt][1] + bq1) * sc1 + of1) > 0.f) ? 1 : 0;
            *(char2*)&OUT[(size_t)r0 * NOUT + N0 + col] = u;
            u.x = ((((float)C_[mt][nt][2] + bq0) * sc0 + of0) > 0.f) ? 1 : 0;
            u.y = ((((float)C_[mt][nt][3] + bq1) * sc1 + of1) > 0.f) ? 1 : 0;
            *(char2*)&OUT[(size_t)(r0 + 8) * NOUT + N0 + col] = u;
        }
}

// ---------------- bitify layer-3 activations -------------------------------------
__global__ __launch_bounds__(256) void bitify_kernel() {
    int idx = blockIdx.x * 256 + threadIdx.x;            // 524288 threads
    const uint4* p = (const uint4*)d_a3s + (size_t)idx * 2;
    uint4 u0 = p[0], u1 = p[1];
    unsigned vs[8] = {u0.x, u0.y, u0.z, u0.w, u1.x, u1.y, u1.z, u1.w};
    unsigned w = 0;
    #pragma unroll
    for (int i = 0; i < 8; i++)
        w |= (((vs[i] & 0x01010101u) * 0x01020408u) >> 24) << (4 * i);
    d_h3[idx] = w;
}

// ---------------- layer 4 + layer 5 + sigmoid (fused popcount) -------------------
__global__ __launch_bounds__(128) void out_kernel(
    const float* __restrict__ b4, const float* __restrict__ g4,
    const float* __restrict__ be4, const float* __restrict__ m4,
    const float* __restrict__ v4, const float* __restrict__ w5,
    const float* __restrict__ b5, float* __restrict__ out)
{
    __shared__ unsigned p4s[64 * 16], n4s[64 * 16];
    __shared__ float sc4[64], off4[64], bb4[64], w5s[64];
    int tid = threadIdx.x;
    for (int i = tid; i < 1024; i += 128) { p4s[i] = d_p4[i]; n4s[i] = d_n4[i]; }
    if (tid < 64) {
        float sc = g4[tid] / sqrtf(v4[tid] + EPSBN);
        sc4[tid] = sc;
        off4[tid] = be4[tid] - m4[tid] * sc;
        bb4[tid]  = b4[tid];
        w5s[tid]  = w5[tid];
    }
    __syncthreads();

    int row = blockIdx.x * 128 + tid;
    unsigned h[16];
    #pragma unroll
    for (int q = 0; q < 4; q++) {
        uint4 t = *(const uint4*)&d_h3[(size_t)row * 16 + q * 4];
        h[q * 4] = t.x; h[q * 4 + 1] = t.y; h[q * 4 + 2] = t.z; h[q * 4 + 3] = t.w;
    }

    float z = b5[0];
    #pragma unroll 4
    for (int j = 0; j < 64; j++) {
        int a = 0, bn = 0;
        #pragma unroll
        for (int k = 0; k < 16; k++) {
            a  += __popc(h[k] & p4s[j * 16 + k]);
            bn += __popc(h[k] & n4s[j * 16 + k]);
        }
        float t = ((float)(a - bn) + bb4[j]) * sc4[j] + off4[j];
        if (t > 0.f) z += w5s[j];
    }
    out[row] = 1.f / (1.f + expf(-z));
}

// ---------------- launch ---------------------------------------------------------
extern "C" void kernel_launch(void* const* d_in, const int* in_sizes, int n_in,
                              void* d_out, int out_size) {
    const float* x   = (const float*)d_in[0];
    const float* w1  = (const float*)d_in[1];
    const float* b1  = (const float*)d_in[2];
    const float* w2  = (const float*)d_in[3];
    const float* b2  = (const float*)d_in[4];
    const float* w3  = (const float*)d_in[5];
    const float* b3  = (const float*)d_in[6];
    const float* w4  = (const float*)d_in[7];
    const float* b4  = (const float*)d_in[8];
    const float* w5  = (const float*)d_in[9];
    const float* b5  = (const float*)d_in[10];
    const float* g1  = (const float*)d_in[11];
    const float* be1 = (const float*)d_in[12];
    const float* m1  = (const float*)d_in[13];
    const float* v1  = (const float*)d_in[14];
    const float* g2  = (const float*)d_in[15];
    const float* be2 = (const float*)d_in[16];
    const float* m2  = (const float*)d_in[17];
    const float* v2  = (const float*)d_in[18];
    const float* g3  = (const float*)d_in[19];
    const float* be3 = (const float*)d_in[20];
    const float* m3  = (const float*)d_in[21];
    const float* v3  = (const float*)d_in[22];
    const float* g4  = (const float*)d_in[23];
    const float* be4 = (const float*)d_in[24];
    const float* m4  = (const float*)d_in[25];
    const float* v4  = (const float*)d_in[26];
    float* out = (float*)d_out;

    cudaFuncSetAttribute(l1mma_kernel, cudaFuncAttributeMaxDynamicSharedMemorySize, L1_SMEM);
    cudaFuncSetAttribute(mmas8_kernel<2>, cudaFuncAttributeMaxDynamicSharedMemorySize, MMAS8_SMEM);
    cudaFuncSetAttribute(mmas8_kernel<3>, cudaFuncAttributeMaxDynamicSharedMemorySize, MMAS8_SMEM);

    pack_all<<<18948, 256>>>(x, w1, w2, w3, w4);
    l1mma_kernel<<<dim3(16, 256), 256, L1_SMEM>>>(b1, g1, be1, m1, v1);
    mmas8_kernel<2><<<dim3(8, 256), 256, MMAS8_SMEM>>>(b2, g2, be2, m2, v2);
    mmas8_kernel<3><<<dim3(4, 256), 256, MMAS8_SMEM>>>(b3, g3, be3, m3, v3);
    bitify_kernel<<<2048, 256>>>();
    out_kernel<<<256, 128>>>(b4, g4, be4, m4, v4, w5, b5, out);
}

// round 7
// speedup vs baseline: 2.6540x; 1.1633x over previous
#include <cuda_runtime.h>
#include <cuda_bf16.h>
#include <math.h>
#include <stdint.h>

// Linear_bin: binarized 5-layer MLP, B=32768, 64->2048->1024->512->64->1.
// L1: bf16 mma GEMM (exact 3-way split of x), epilogue emits A-fragments for L2.
// L2, L3: s8 mma.m16n8k32 GEMMs with ZERO smem in the mainloop:
//         A and B both loaded as pre-packed mma fragments via coalesced LDG.128.
// L4+L5+sigmoid: fused popcount kernel.

#define BATCH 32768
#define EPSBN 1e-5f

// ---------------- scratch (static device globals; no allocation) ----------------
__device__ __align__(16) __nv_bfloat16 d_xp[BATCH * 192];     // x split: hi|mid|lo
__device__ __align__(16) unsigned short d_w1b[2048 * 192];    // sign(w1) bf16, 3x replicated
__device__ __align__(16) uint4 d_w2f[(1024 / 16) * 64 * 32];  // sign(w2) B-fragments
__device__ __align__(16) uint4 d_w3f[(512 / 16) * 32 * 32];   // sign(w3) B-fragments
__device__ __align__(16) uint4 d_a1f[2048 * 64 * 32];         // L1 acts as L2 A-fragments (64MB)
__device__ __align__(16) uint4 d_a2f[2048 * 32 * 32];         // L2 acts as L3 A-fragments (32MB)
__device__ unsigned d_p4[64 * 16];
__device__ unsigned d_n4[64 * 16];
__device__ __align__(16) char  d_a3s[BATCH * 512];            // L3 acts {0,1} row-major
__device__ __align__(16) unsigned d_h3[BATCH * 16];           // L3 bits

// ---------------- helpers --------------------------------------------------------
__device__ __forceinline__ uint32_t smem_u32(const void* p) {
    uint32_t a;
    asm("{ .reg .u64 t; cvta.to.shared.u64 t, %1; cvt.u32.u64 %0, t; }" : "=r"(a) : "l"(p));
    return a;
}
#define LDMX4(r, a) \
    asm volatile("ldmatrix.sync.aligned.m8n8.x4.shared.b16 {%0,%1,%2,%3}, [%4];" \
        : "=r"((r)[0]), "=r"((r)[1]), "=r"((r)[2]), "=r"((r)[3]) : "r"(a))

__device__ __forceinline__ void mma_s8(int* c, const uint32_t* a, uint32_t b0, uint32_t b1) {
    asm volatile(
        "mma.sync.aligned.m16n8k32.row.col.s32.s8.s8.s32 "
        "{%0,%1,%2,%3}, {%4,%5,%6,%7}, {%8,%9}, {%0,%1,%2,%3};"
        : "+r"(c[0]), "+r"(c[1]), "+r"(c[2]), "+r"(c[3])
        : "r"(a[0]), "r"(a[1]), "r"(a[2]), "r"(a[3]), "r"(b0), "r"(b1));
}
__device__ __forceinline__ void mma_bf16(float* c, const uint32_t* a, uint32_t b0, uint32_t b1) {
    asm volatile(
        "mma.sync.aligned.m16n8k16.row.col.f32.bf16.bf16.f32 "
        "{%0,%1,%2,%3}, {%4,%5,%6,%7}, {%8,%9}, {%0,%1,%2,%3};"
        : "+f"(c[0]), "+f"(c[1]), "+f"(c[2]), "+f"(c[3])
        : "r"(a[0]), "r"(a[1]), "r"(a[2]), "r"(a[3]), "r"(b0), "r"(b1));
}
__device__ __forceinline__ void cp16(uint32_t dst, const void* src) {
    asm volatile("cp.async.cg.shared.global [%0], [%1], 16;" :: "r"(dst), "l"(src));
}
// 384-byte rows (K=192 bf16): swizzle within each 128B third
__device__ __forceinline__ uint32_t swz384(int r, int s) {
    return (uint32_t)(r * 384 + (((s & 24) | ((s ^ r) & 7)) << 4));
}
__device__ __forceinline__ unsigned sgn4(const float* p) {
    unsigned r = 0;
    #pragma unroll
    for (int j = 0; j < 4; j++) {
        float v = p[j];
        int s = (v > 0.f) ? 1 : ((v < 0.f) ? -1 : 0);
        r |= ((unsigned)(s & 0xff)) << (8 * j);
    }
    return r;
}

// ---- fragment-emission epilogue core: given 4 nt-packed bit words, build and
//      store one A-fragment uint4 (shared by l1 and l2 epilogues).
__device__ __forceinline__ void emit_afrag(
    uint4* dst, unsigned lo0, unsigned lo1, unsigned lo2, unsigned lo3,
    unsigned hi0, unsigned hi1, unsigned hi2, unsigned hi3, int lane)
{
    unsigned ploA = lo0 | (lo1 << 16), ploB = lo2 | (lo3 << 16);
    unsigned phiA = hi0 | (hi1 << 16), phiB = hi2 | (hi3 << 16);
    int s0 = 4 * (lane >> 2) + 2 * (lane & 1);
    unsigned selm = (lane & 2) ? 0x7632u : 0x5410u;
    uint4 o;
    o.x = __byte_perm(__shfl_sync(0xffffffffu, ploA, s0),
                      __shfl_sync(0xffffffffu, ploA, s0 + 1), selm);
    o.y = __byte_perm(__shfl_sync(0xffffffffu, phiA, s0),
                      __shfl_sync(0xffffffffu, phiA, s0 + 1), selm);
    o.z = __byte_perm(__shfl_sync(0xffffffffu, ploB, s0),
                      __shfl_sync(0xffffffffu, ploB, s0 + 1), selm);
    o.w = __byte_perm(__shfl_sync(0xffffffffu, phiB, s0),
                      __shfl_sync(0xffffffffu, phiB, s0 + 1), selm);
    *dst = o;
}

// ---------------- weight preprocessing + x split ---------------------------------
// threads: w1b 131072 | xp 2097152 | w2f 131072 | w3f 32768 | w4 1024 = 2393088
__global__ void pack_all(const float* __restrict__ x,  const float* __restrict__ w1,
                         const float* __restrict__ w2, const float* __restrict__ w3,
                         const float* __restrict__ w4) {
    long idx = (long)blockIdx.x * 256 + threadIdx.x;
    if (idx < 131072) {                                  // sign(w1) bf16, replicated x3
        int n = (int)idx >> 6, k = (int)idx & 63;
        float v = w1[n * 64 + k];
        unsigned short s = (v > 0.f) ? 0x3F80 : ((v < 0.f) ? 0xBF80 : 0);
        d_w1b[n * 192 + k] = s;
        d_w1b[n * 192 + k + 64] = s;
        d_w1b[n * 192 + k + 128] = s;
    } else if (idx < 131072 + 2097152) {                 // x 3-way exact bf16 split
        int i = (int)(idx - 131072);
        int row = i >> 6, k = i & 63;
        float v = x[i];
        __nv_bfloat16 hi = __float2bfloat16(v);
        float r1 = v - __bfloat162float(hi);
        __nv_bfloat16 mid = __float2bfloat16(r1);
        float r2 = r1 - __bfloat162float(mid);
        __nv_bfloat16 lo = __float2bfloat16(r2);
        d_xp[(size_t)row * 192 + k]       = hi;
        d_xp[(size_t)row * 192 + k + 64]  = mid;
        d_xp[(size_t)row * 192 + k + 128] = lo;
    } else if (idx < 131072 + 2097152 + 131072) {        // sign(w2) B-fragments
        int i = (int)(idx - 131072 - 2097152);
        int nq = i >> 11, kc = (i >> 5) & 63, lane = i & 31;
        int col = nq * 16 + (lane >> 2);
        int kb  = kc * 32 + (lane & 3) * 4;
        const float* p0 = w2 + (size_t)col * 2048 + kb;
        const float* p1 = p0 + 8 * 2048;
        uint4 o;
        o.x = sgn4(p0); o.y = sgn4(p0 + 16);
        o.z = sgn4(p1); o.w = sgn4(p1 + 16);
        d_w2f[i] = o;
    } else if (idx < 131072 + 2097152 + 131072 + 32768) { // sign(w3) B-fragments
        int i = (int)(idx - 131072 - 2097152 - 131072);
        int nq = i >> 10, kc = (i >> 5) & 31, lane = i & 31;
        int col = nq * 16 + (lane >> 2);
        int kb  = kc * 32 + (lane & 3) * 4;
        const float* p0 = w3 + (size_t)col * 1024 + kb;
        const float* p1 = p0 + 8 * 1024;
        uint4 o;
        o.x = sgn4(p0); o.y = sgn4(p0 + 16);
        o.z = sgn4(p1); o.w = sgn4(p1 + 16);
        d_w3f[i] = o;
    } else if (idx < 131072 + 2097152 + 131072 + 32768 + 1024) { // w4 bitmasks
        int t = (int)(idx - 131072 - 2097152 - 131072 - 32768);
        int j = t >> 4, w = t & 15;
        unsigned p = 0, n = 0;
        #pragma unroll
        for (int i = 0; i < 32; i++) {
            float v = w4[j * 512 + w * 32 + i];
            if (v > 0.f) p |= (1u << i);
            if (v < 0.f) n |= (1u << i);
        }
        d_p4[j * 16 + w] = p;
        d_n4[j * 16 + w] = n;
    }
}

// ---------------- layer 1: bf16 mma GEMM (M=32768, N=2048, K=192) ----------------
// CTA tile 128x128, K fully resident. Epilogue emits L2 A-fragments.
#define L1_SMEM (49152 + 49152 + 3 * 512)
__global__ __launch_bounds__(256, 2) void l1mma_kernel(
    const float* __restrict__ b1, const float* __restrict__ g1,
    const float* __restrict__ be1, const float* __restrict__ m1,
    const float* __restrict__ v1)
{
    extern __shared__ __align__(128) char smem[];
    uint32_t sb = smem_u32(smem);
    float* ssc = (float*)(smem + 98304);
    float* sof = (float*)(smem + 98816);
    float* sbb = (float*)(smem + 99328);

    int tid = threadIdx.x, wid = tid >> 5, lane = tid & 31;
    int N0 = blockIdx.x * 128, R0 = blockIdx.y * 128;
    int warpM = (wid & 3) * 32, warpN = (wid >> 2) * 64;
    uint32_t ab = sb, bb = sb + 49152;

    const char* Ag = (const char*)(d_xp + (size_t)R0 * 192);
    const char* Wg = (const char*)(d_w1b + (size_t)N0 * 192);
    #pragma unroll
    for (int i = 0; i < 12; i++) {
        int idx = tid + i * 256;
        int r = idx / 24, sg = idx % 24;
        cp16(ab + swz384(r, sg), Ag + (size_t)r * 384 + sg * 16);
        cp16(bb + swz384(r, sg), Wg + (size_t)r * 384 + sg * 16);
    }
    asm volatile("cp.async.commit_group;");

    for (int t = tid; t < 128; t += 256) {
        int j = N0 + t;
        float sc = g1[j] / sqrtf(v1[j] + EPSBN);
        ssc[t] = sc;
        sof[t] = be1[j] - m1[j] * sc;
        sbb[t] = b1[j];
    }
    float C_[2][8][4];
    #pragma unroll
    for (int mt = 0; mt < 2; mt++)
        #pragma unroll
        for (int nt = 0; nt < 8; nt++)
            #pragma unroll
            for (int q = 0; q < 4; q++) C_[mt][nt][q] = 0.f;

    asm volatile("cp.async.wait_group 0;");
    __syncthreads();

    #pragma unroll
    for (int ks = 0; ks < 12; ks++) {
        uint32_t af[2][4];
        #pragma unroll
        for (int mt = 0; mt < 2; mt++) {
            int row = warpM + mt * 16 + (lane & 7) + ((lane >> 3) & 1) * 8;
            int sg  = ks * 2 + (lane >> 4);
            LDMX4(af[mt], ab + swz384(row, sg));
        }
        uint32_t bf[4][4];
        #pragma unroll
        for (int p = 0; p < 4; p++) {
            int row = warpN + p * 16 + (lane & 7) + (lane >> 4) * 8;
            int sg  = ks * 2 + ((lane >> 3) & 1);
            LDMX4(bf[p], bb + swz384(row, sg));
        }
        #pragma unroll
        for (int mt = 0; mt < 2; mt++)
            #pragma unroll
            for (int p = 0; p < 4; p++) {
                mma_bf16(C_[mt][2 * p],     af[mt], bf[p][0], bf[p][1]);
                mma_bf16(C_[mt][2 * p + 1], af[mt], bf[p][2], bf[p][3]);
            }
    }

    // epilogue: BN + threshold -> L2 A-fragments (KC = 64)
    #pragma unroll
    for (int mt = 0; mt < 2; mt++) {
        int rt = (R0 + warpM + mt * 16) >> 4;
        #pragma unroll
        for (int kc2 = 0; kc2 < 2; kc2++) {
            unsigned lo[4], hi[4];
            #pragma unroll
            for (int i = 0; i < 4; i++) {
                int nt = kc2 * 4 + i;
                int col = warpN + nt * 8 + (lane & 3) * 2;
                float sc0 = ssc[col],     of0 = sof[col],     bq0 = sbb[col];
                float sc1 = ssc[col + 1], of1 = sof[col + 1], bq1 = sbb[col + 1];
                unsigned b0 = (((C_[mt][nt][0] + bq0) * sc0 + of0) > 0.f) ? 1u : 0u;
                unsigned b1 = (((C_[mt][nt][1] + bq1) * sc1 + of1) > 0.f) ? 1u : 0u;
                unsigned b2 = (((C_[mt][nt][2] + bq0) * sc0 + of0) > 0.f) ? 1u : 0u;
                unsigned b3 = (((C_[mt][nt][3] + bq1) * sc1 + of1) > 0.f) ? 1u : 0u;
                lo[i] = b0 | (b1 << 8);
                hi[i] = b2 | (b3 << 8);
            }
            int kcg = ((N0 + warpN) >> 5) + kc2;
            emit_afrag(&d_a1f[((size_t)rt * 64 + kcg) * 32 + lane],
                       lo[0], lo[1], lo[2], lo[3], hi[0], hi[1], hi[2], hi[3], lane);
        }
    }
}

// ---------------- layers 2/3: s8 mma GEMM, smem-free fragment mainloop -----------
template<int LAYER>
__global__ __launch_bounds__(256, 2) void mmas8_kernel(
    const float* __restrict__ bbp, const float* __restrict__ g,
    const float* __restrict__ be, const float* __restrict__ m,
    const float* __restrict__ v)
{
    constexpr int KDIM = (LAYER == 2) ? 2048 : 1024;
    constexpr int NOUT = (LAYER == 2) ? 1024 : 512;
    constexpr int KC   = KDIM / 32;
    const uint4* __restrict__ Af = (LAYER == 2) ? d_a1f : d_a2f;
    const uint4* __restrict__ Wf = (LAYER == 2) ? d_w2f : d_w3f;

    __shared__ float ssc[128], sof[128], sbb[128];

    int tid = threadIdx.x, wid = tid >> 5, lane = tid & 31;
    int N0 = blockIdx.x * 128, R0 = blockIdx.y * 128;
    int warpM = (wid & 3) * 32, warpN = (wid >> 2) * 64;

    if (tid < 128) {
        int j = N0 + tid;
        float sc = g[j] / sqrtf(v[j] + EPSBN);
        ssc[tid] = sc;
        sof[tid] = be[j] - m[j] * sc;
        sbb[tid] = bbp[j];
    }
    __syncthreads();

    int rt0 = (R0 + warpM) >> 4;
    int nq0 = (N0 + warpN) >> 4;
    const uint4* Ap0 = Af + ((size_t)rt0 * KC) * 32 + lane;
    const uint4* Ap1 = Af + ((size_t)(rt0 + 1) * KC) * 32 + lane;
    const uint4* Bp0 = Wf + ((size_t)nq0 * KC) * 32 + lane;
    const uint4* Bp1 = Wf + ((size_t)(nq0 + 1) * KC) * 32 + lane;
    const uint4* Bp2 = Wf + ((size_t)(nq0 + 2) * KC) * 32 + lane;
    const uint4* Bp3 = Wf + ((size_t)(nq0 + 3) * KC) * 32 + lane;

    int C_[2][8][4];
    #pragma unroll
    for (int mt = 0; mt < 2; mt++)
        #pragma unroll
        for (int nt = 0; nt < 8; nt++)
            #pragma unroll
            for (int q = 0; q < 4; q++) C_[mt][nt][q] = 0;

    #pragma unroll 2
    for (int kc = 0; kc < KC; kc++) {
        uint4 a0 = Ap0[kc * 32];
        uint4 a1 = Ap1[kc * 32];
        uint4 b0 = Bp0[kc * 32];
        uint4 b1 = Bp1[kc * 32];
        uint4 b2 = Bp2[kc * 32];
        uint4 b3 = Bp3[kc * 32];
        const uint32_t* A0 = (const uint32_t*)&a0;
        const uint32_t* A1 = (const uint32_t*)&a1;
        mma_s8(C_[0][0], A0, b0.x, b0.y);  mma_s8(C_[0][1], A0, b0.z, b0.w);
        mma_s8(C_[0][2], A0, b1.x, b1.y);  mma_s8(C_[0][3], A0, b1.z, b1.w);
        mma_s8(C_[0][4], A0, b2.x, b2.y);  mma_s8(C_[0][5], A0, b2.z, b2.w);
        mma_s8(C_[0][6], A0, b3.x, b3.y);  mma_s8(C_[0][7], A0, b3.z, b3.w);
        mma_s8(C_[1][0], A1, b0.x, b0.y);  mma_s8(C_[1][1], A1, b0.z, b0.w);
        mma_s8(C_[1][2], A1, b1.x, b1.y);  mma_s8(C_[1][3], A1, b1.z, b1.w);
        mma_s8(C_[1][4], A1, b2.x, b2.y);  mma_s8(C_[1][5], A1, b2.z, b2.w);
        mma_s8(C_[1][6], A1, b3.x, b3.y);  mma_s8(C_[1][7], A1, b3.z, b3.w);
    }

    if (LAYER == 2) {
        // epilogue: BN + threshold -> L3 A-fragments (KC_out = 32)
        #pragma unroll
        for (int mt = 0; mt < 2; mt++) {
            int rt = (R0 + warpM + mt * 16) >> 4;
            #pragma unroll
            for (int kc2 = 0; kc2 < 2; kc2++) {
                unsigned lo[4], hi[4];
                #pragma unroll
                for (int i = 0; i < 4; i++) {
                    int nt = kc2 * 4 + i;
                    int col = warpN + nt * 8 + (lane & 3) * 2;
                    float sc0 = ssc[col],     of0 = sof[col],     bq0 = sbb[col];
                    float sc1 = ssc[col + 1], of1 = sof[col + 1], bq1 = sbb[col + 1];
                    unsigned b0 = ((((float)C_[mt][nt][0] + bq0) * sc0 + of0) > 0.f) ? 1u : 0u;
                    unsigned b1 = ((((float)C_[mt][nt][1] + bq1) * sc1 + of1) > 0.f) ? 1u : 0u;
                    unsigned b2 = ((((float)C_[mt][nt][2] + bq0) * sc0 + of0) > 0.f) ? 1u : 0u;
                    unsigned b3 = ((((float)C_[mt][nt][3] + bq1) * sc1 + of1) > 0.f) ? 1u : 0u;
                    lo[i] = b0 | (b1 << 8);
                    hi[i] = b2 | (b3 << 8);
                }
                int kcg = ((N0 + warpN) >> 5) + kc2;
                emit_afrag(&d_a2f[((size_t)rt * 32 + kcg) * 32 + lane],
                           lo[0], lo[1], lo[2], lo[3], hi[0], hi[1], hi[2], hi[3], lane);
            }
        }
    } else {
        // epilogue: BN + threshold -> row-major s8 (for bitify)
        #pragma unroll
        for (int mt = 0; mt < 2; mt++)
            #pragma unroll
            for (int nt = 0; nt < 8; nt++) {
                int col = warpN + nt * 8 + (lane & 3) * 2;
                int r0  = R0 + warpM + mt * 16 + (lane >> 2);
                float sc0 = ssc[col],     of0 = sof[col],     bq0 = sbb[col];
                float sc1 = ssc[col + 1], of1 = sof[col + 1], bq1 = sbb[col + 1];
                char2 u;
                u.x = ((((float)C_[mt][nt][0] + bq0) * sc0 + of0) > 0.f) ? 1 : 0;
                u.y = ((((float)C_[mt][nt][1] + bq1) * sc1 + of1) > 0.f) ? 1 : 0;
                *(char2*)&d_a3s[(size_t)r0 * NOUT + N0 + col] = u;
                u.x = ((((float)C_[mt][nt][2] + bq0) * sc0 + of0) > 0.f) ? 1 : 0;
                u.y = ((((float)C_[mt][nt][3] + bq1) * sc1 + of1) > 0.f) ? 1 : 0;
                *(char2*)&d_a3s[(size_t)(r0 + 8) * NOUT + N0 + col] = u;
            }
    }
}

// ---------------- bitify layer-3 activations -------------------------------------
__global__ __launch_bounds__(256) void bitify_kernel() {
    int idx = blockIdx.x * 256 + threadIdx.x;            // 524288 threads
    const uint4* p = (const uint4*)d_a3s + (size_t)idx * 2;
    uint4 u0 = p[0], u1 = p[1];
    unsigned vs[8] = {u0.x, u0.y, u0.z, u0.w, u1.x, u1.y, u1.z, u1.w};
    unsigned w = 0;
    #pragma unroll
    for (int i = 0; i < 8; i++)
        w |= (((vs[i] & 0x01010101u) * 0x01020408u) >> 24) << (4 * i);
    d_h3[idx] = w;
}

// ---------------- layer 4 + layer 5 + sigmoid (fused popcount) -------------------
__global__ __launch_bounds__(128) void out_kernel(
    const float* __restrict__ b4, const float* __restrict__ g4,
    const float* __restrict__ be4, const float* __restrict__ m4,
    const float* __restrict__ v4, const float* __restrict__ w5,
    const float* __restrict__ b5, float* __restrict__ out)
{
    __shared__ unsigned p4s[64 * 16], n4s[64 * 16];
    __shared__ float sc4[64], off4[64], bb4[64], w5s[64];
    int tid = threadIdx.x;
    for (int i = tid; i < 1024; i += 128) { p4s[i] = d_p4[i]; n4s[i] = d_n4[i]; }
    if (tid < 64) {
        float sc = g4[tid] / sqrtf(v4[tid] + EPSBN);
        sc4[tid] = sc;
        off4[tid] = be4[tid] - m4[tid] * sc;
        bb4[tid]  = b4[tid];
        w5s[tid]  = w5[tid];
    }
    __syncthreads();

    int row = blockIdx.x * 128 + tid;
    unsigned h[16];
    #pragma unroll
    for (int q = 0; q < 4; q++) {
        uint4 t = *(const uint4*)&d_h3[(size_t)row * 16 + q * 4];
        h[q * 4] = t.x; h[q * 4 + 1] = t.y; h[q * 4 + 2] = t.z; h[q * 4 + 3] = t.w;
    }

    float z = b5[0];
    #pragma unroll 4
    for (int j = 0; j < 64; j++) {
        int a = 0, bn = 0;
        #pragma unroll
        for (int k = 0; k < 16; k++) {
            a  += __popc(h[k] & p4s[j * 16 + k]);
            bn += __popc(h[k] & n4s[j * 16 + k]);
        }
        float t = ((float)(a - bn) + bb4[j]) * sc4[j] + off4[j];
        if (t > 0.f) z += w5s[j];
    }
    out[row] = 1.f / (1.f + expf(-z));
}

// ---------------- launch ---------------------------------------------------------
extern "C" void kernel_launch(void* const* d_in, const int* in_sizes, int n_in,
                              void* d_out, int out_size) {
    const float* x   = (const float*)d_in[0];
    const float* w1  = (const float*)d_in[1];
    const float* b1  = (const float*)d_in[2];
    const float* w2  = (const float*)d_in[3];
    const float* b2  = (const float*)d_in[4];
    const float* w3  = (const float*)d_in[5];
    const float* b3  = (const float*)d_in[6];
    const float* w4  = (const float*)d_in[7];
    const float* b4  = (const float*)d_in[8];
    const float* w5  = (const float*)d_in[9];
    const float* b5  = (const float*)d_in[10];
    const float* g1  = (const float*)d_in[11];
    const float* be1 = (const float*)d_in[12];
    const float* m1  = (const float*)d_in[13];
    const float* v1  = (const float*)d_in[14];
    const float* g2  = (const float*)d_in[15];
    const float* be2 = (const float*)d_in[16];
    const float* m2  = (const float*)d_in[17];
    const float* v2  = (const float*)d_in[18];
    const float* g3  = (const float*)d_in[19];
    const float* be3 = (const float*)d_in[20];
    const float* m3  = (const float*)d_in[21];
    const float* v3  = (const float*)d_in[22];
    const float* g4  = (const float*)d_in[23];
    const float* be4 = (const float*)d_in[24];
    const float* m4  = (const float*)d_in[25];
    const float* v4  = (const float*)d_in[26];
    float* out = (float*)d_out;

    cudaFuncSetAttribute(l1mma_kernel, cudaFuncAttributeMaxDynamicSharedMemorySize, L1_SMEM);

    pack_all<<<9348, 256>>>(x, w1, w2, w3, w4);
    l1mma_kernel<<<dim3(16, 256), 256, L1_SMEM>>>(b1, g1, be1, m1, v1);
    mmas8_kernel<2><<<dim3(8, 256), 256>>>(b2, g2, be2, m2, v2);
    mmas8_kernel<3><<<dim3(4, 256), 256>>>(b3, g3, be3, m3, v3);
    bitify_kernel<<<2048, 256>>>();
    out_kernel<<<256, 128>>>(b4, g4, be4, m4, v4, w5, b5, out);
}